// round 3
// baseline (speedup 1.0000x reference)
#include <cuda_runtime.h>
#include <math.h>

// Problem constants
#define CC   128          // channels
#define HH   256
#define WWD  256
#define HW   65536        // H*W
#define XW_S 129          // x-window smem stride (64 x 128 padded)
#define QKV_S 385         // qkv smem stride (64 x 384 padded)
#define WT_S 133          // transposed weight tile stride (128 wide padded; 133 mod 32 = 5 -> conflict-free)

// Scratch (device globals per harness rules: no cudaMalloc allowed)
__device__ float g_bias[64 * 64];
__device__ float g_x2[4 * CC * HW];   // x + attention (residual stream), 128 MB
__device__ float g_y1[4 * CC * HW];   // gelu(conv1x1(x2)), 128 MB

__device__ __forceinline__ float gelu_exact(float v) {
    return 0.5f * v * (1.0f + erff(v * 0.70710678118654752440f));
}

extern __shared__ float smem[];

// ---------------------------------------------------------------------------
// Kernel 0: relative-position bias MLP. bias[n*64+m] for the 64x64 window.
// ---------------------------------------------------------------------------
__global__ void k_bias(const float* __restrict__ delta, const int* __restrict__ index,
                       const float* __restrict__ w_b1, const float* __restrict__ b_b1,
                       const float* __restrict__ w_b2, const float* __restrict__ b_b2) {
    int t = blockIdx.x * blockDim.x + threadIdx.x;
    if (t >= 4096) return;
    int u = index[t];
    float dx = delta[2 * u], dy = delta[2 * u + 1];
    float acc = b_b2[0];
#pragma unroll
    for (int j = 0; j < 16; ++j) {
        float h = dx * w_b1[2 * j] + dy * w_b1[2 * j + 1] + b_b1[j];
        acc += w_b2[j] * gelu_exact(h);
    }
    g_bias[t] = acc;
}

// ---------------------------------------------------------------------------
// Kernel 1: window attention. One 256-thread block per 8x8 window (4096 blocks).
// Dynamic smem layout:
//   xw  : 64 x XW_S   (x window; reused as attention output after qkv phase)
//   qkv : 64 x QKV_S  (q|k|v, 384 cols)
//   wt  : 128 x WT_S  (transposed weight tile; reused as 64x66 score buffer)
// Writes g_x2 = x + attn_out.
// ---------------------------------------------------------------------------
__global__ void __launch_bounds__(256, 1)
k_attn(const float* __restrict__ x,
       const float* __restrict__ w_qkv, const float* __restrict__ b_qkv,
       const float* __restrict__ w_head, const float* __restrict__ b_head) {
    float* xw  = smem;                       // 64*129 = 8256
    float* qkv = smem + 64 * XW_S;           // 64*385 = 24640
    float* wt  = qkv + 64 * QKV_S;           // 128*133 = 17024

    const int tid = threadIdx.x;
    const int warp = tid >> 5, lane = tid & 31;
    const int wid = blockIdx.x;
    const int b   = wid >> 10;
    const int ohi = (wid >> 5) & 31;
    const int owi = wid & 31;
    const float* xptr = x + (size_t)b * CC * HW + ohi * 8 * WWD + owi * 8;
    const int n0 = warp * 8;   // this warp's 8 token rows

    // ---- load x window [64 tokens][128 ch] ----
    for (int e = tid; e < 64 * 128; e += 256) {
        int c = e >> 6, n = e & 63;
        xw[n * XW_S + c] = xptr[(size_t)c * HW + (n >> 3) * WWD + (n & 7)];
    }

    // ---- qkv = xw @ w_qkv^T + b_qkv (three 128-wide output tiles) ----
    for (int t3 = 0; t3 < 3; ++t3) {
        __syncthreads();
        for (int e = tid; e < 128 * 128; e += 256) {
            int c = e & 127, o = e >> 7;
            wt[c * WT_S + o] = w_qkv[(size_t)(t3 * 128 + o) * 128 + c];
        }
        __syncthreads();
        float acc[8][4];
#pragma unroll
        for (int j = 0; j < 4; ++j) {
            float bq = b_qkv[t3 * 128 + lane + 32 * j];
#pragma unroll
            for (int i = 0; i < 8; ++i) acc[i][j] = bq;
        }
        for (int c = 0; c < 128; ++c) {
            float w0 = wt[c * WT_S + lane];
            float w1 = wt[c * WT_S + lane + 32];
            float w2 = wt[c * WT_S + lane + 64];
            float w3 = wt[c * WT_S + lane + 96];
#pragma unroll
            for (int i = 0; i < 8; ++i) {
                float xv = xw[(n0 + i) * XW_S + c];
                acc[i][0] += xv * w0; acc[i][1] += xv * w1;
                acc[i][2] += xv * w2; acc[i][3] += xv * w3;
            }
        }
#pragma unroll
        for (int i = 0; i < 8; ++i)
#pragma unroll
            for (int j = 0; j < 4; ++j)
                qkv[(n0 + i) * QKV_S + t3 * 128 + lane + 32 * j] = acc[i][j];
    }
    __syncthreads();

    float* sc = wt;   // 64 x 66 score buffer (wt region, free now)
    float* ao = xw;   // attention output (xw region, free now)

    for (int h = 0; h < 2; ++h) {
        const int qo = h * 64, ko = 128 + h * 64, vo = 256 + h * 64;
        // scores = q k^T / 8 + bias  (warp: 8 rows; lane: cols m=lane, lane+32)
        {
            float a0[8], a1[8];
#pragma unroll
            for (int i = 0; i < 8; ++i) { a0[i] = 0.f; a1[i] = 0.f; }
            for (int d = 0; d < 64; ++d) {
                float k0 = qkv[lane * QKV_S + ko + d];
                float k1 = qkv[(lane + 32) * QKV_S + ko + d];
#pragma unroll
                for (int i = 0; i < 8; ++i) {
                    float qv = qkv[(n0 + i) * QKV_S + qo + d];
                    a0[i] += qv * k0; a1[i] += qv * k1;
                }
            }
#pragma unroll
            for (int i = 0; i < 8; ++i) {
                int n = n0 + i;
                sc[n * 66 + lane]      = a0[i] * 0.125f + g_bias[n * 64 + lane];
                sc[n * 66 + lane + 32] = a1[i] * 0.125f + g_bias[n * 64 + lane + 32];
            }
        }
        __syncthreads();
        // softmax: 4 threads per row, 16 contiguous elems each, shfl-reduce
        {
            int row = tid >> 2, sub = tid & 3;
            float* r = sc + row * 66 + sub * 16;
            float v[16];
            float mx = -1e30f;
#pragma unroll
            for (int m = 0; m < 16; ++m) { v[m] = r[m]; mx = fmaxf(mx, v[m]); }
            mx = fmaxf(mx, __shfl_xor_sync(0xffffffffu, mx, 1));
            mx = fmaxf(mx, __shfl_xor_sync(0xffffffffu, mx, 2));
            float s = 0.f;
#pragma unroll
            for (int m = 0; m < 16; ++m) { v[m] = __expf(v[m] - mx); s += v[m]; }
            s += __shfl_xor_sync(0xffffffffu, s, 1);
            s += __shfl_xor_sync(0xffffffffu, s, 2);
            float inv = 1.f / s;
#pragma unroll
            for (int m = 0; m < 16; ++m) r[m] = v[m] * inv;
        }
        __syncthreads();
        // o = attn @ v  (warp: 8 rows; lane: dims d=lane, lane+32)
        {
            float a0[8], a1[8];
#pragma unroll
            for (int i = 0; i < 8; ++i) { a0[i] = 0.f; a1[i] = 0.f; }
            for (int m = 0; m < 64; ++m) {
                float v0 = qkv[m * QKV_S + vo + lane];
                float v1 = qkv[m * QKV_S + vo + lane + 32];
#pragma unroll
                for (int i = 0; i < 8; ++i) {
                    float p = sc[(n0 + i) * 66 + m];
                    a0[i] += p * v0; a1[i] += p * v1;
                }
            }
#pragma unroll
            for (int i = 0; i < 8; ++i) {
                ao[(n0 + i) * XW_S + h * 64 + lane]      = a0[i];
                ao[(n0 + i) * XW_S + h * 64 + lane + 32] = a1[i];
            }
        }
        __syncthreads();
    }

    // ---- head projection + residual: x2 = x + ao @ w_head^T + b_head ----
    for (int e = tid; e < 128 * 128; e += 256) {
        int cp = e & 127, c = e >> 7;
        wt[cp * WT_S + c] = w_head[(size_t)c * 128 + cp];
    }
    __syncthreads();
    float acc[8][4];
#pragma unroll
    for (int j = 0; j < 4; ++j) {
        float bh = b_head[lane + 32 * j];
#pragma unroll
        for (int i = 0; i < 8; ++i) acc[i][j] = bh;
    }
    for (int cp = 0; cp < 128; ++cp) {
        float w0 = wt[cp * WT_S + lane];
        float w1 = wt[cp * WT_S + lane + 32];
        float w2 = wt[cp * WT_S + lane + 64];
        float w3 = wt[cp * WT_S + lane + 96];
#pragma unroll
        for (int i = 0; i < 8; ++i) {
            float av = ao[(n0 + i) * XW_S + cp];
            acc[i][0] += av * w0; acc[i][1] += av * w1;
            acc[i][2] += av * w2; acc[i][3] += av * w3;
        }
    }
    // warp's 8 tokens are one window row r=warp, cols 0..7
#pragma unroll
    for (int j = 0; j < 4; ++j) {
        int c = lane + 32 * j;
        const float* xrow = xptr + (size_t)c * HW + warp * WWD;
        float* orow = g_x2 + ((size_t)(b * CC + c)) * HW + (ohi * 8 + warp) * WWD + owi * 8;
#pragma unroll
        for (int i = 0; i < 8; ++i)
            orow[i] = acc[i][j] + xrow[i];
    }
}

// ---------------------------------------------------------------------------
// Kernel 2: 1x1 conv + exact GELU. One block = 64 consecutive pixels x 128 co.
// ---------------------------------------------------------------------------
__global__ void __launch_bounds__(256)
k_conv1(const float* __restrict__ w_c1, const float* __restrict__ b_c1) {
    float* xt  = smem;               // 128 ci x 65 (64 px padded)
    float* wct = smem + 128 * 65;    // 128 ci x WT_S (transposed weights)
    const int tid = threadIdx.x, warp = tid >> 5, lane = tid & 31;
    const int pid0 = blockIdx.x * 64;
    const int b = pid0 >> 16;
    const int hw0 = pid0 & 65535;
    const float* xin = g_x2 + (size_t)b * CC * HW + hw0;

    for (int e = tid; e < 128 * 128; e += 256) {
        int ci = e & 127, co = e >> 7;
        wct[ci * WT_S + co] = w_c1[(size_t)co * 128 + ci];
    }
    for (int e = tid; e < 128 * 64; e += 256) {
        int ci = e >> 6, p = e & 63;
        xt[ci * 65 + p] = xin[(size_t)ci * HW + p];
    }
    __syncthreads();

    float acc[8][4];
#pragma unroll
    for (int j = 0; j < 4; ++j) {
        float bc = b_c1[lane + 32 * j];
#pragma unroll
        for (int i = 0; i < 8; ++i) acc[i][j] = bc;
    }
    const int p0 = warp * 8;
    for (int ci = 0; ci < 128; ++ci) {
        float w0 = wct[ci * WT_S + lane];
        float w1 = wct[ci * WT_S + lane + 32];
        float w2 = wct[ci * WT_S + lane + 64];
        float w3 = wct[ci * WT_S + lane + 96];
#pragma unroll
        for (int i = 0; i < 8; ++i) {
            float xv = xt[ci * 65 + p0 + i];
            acc[i][0] += xv * w0; acc[i][1] += xv * w1;
            acc[i][2] += xv * w2; acc[i][3] += xv * w3;
        }
    }
    float* yout = g_y1 + (size_t)b * CC * HW + hw0;
#pragma unroll
    for (int j = 0; j < 4; ++j) {
        int co = lane + 32 * j;
#pragma unroll
        for (int i = 0; i < 8; ++i)
            yout[(size_t)co * HW + p0 + i] = gelu_exact(acc[i][j]);
    }
}

// ---------------------------------------------------------------------------
// Kernel 3: edge-padded 3x3 conv + LeakyReLU(0.1) + residual -> out.
// Block: 4 rows x 64 cols pixel tile x 32 co chunk. ci processed in 8-chunks.
// Edge replication baked into the halo smem load via clamping.
// ---------------------------------------------------------------------------
__global__ void __launch_bounds__(256)
k_conv2(const float* __restrict__ w_c2, const float* __restrict__ b_c2,
        float* __restrict__ out) {
    __shared__ float yt[8 * 6 * 66];   // 8 ci x (4+2) rows x (64+2) cols halo tile
    __shared__ float wct[8 * 9 * 33];  // 8 ci x 9 taps x 32 co (+pad)
    const int tid = threadIdx.x, warp = tid >> 5, lane = tid & 31;
    const int cochunk = blockIdx.x & 3;
    const int tile = blockIdx.x >> 2;
    const int b = tile >> 8;
    const int t = tile & 255;
    const int h0 = (t >> 2) * 4;
    const int w0 = (t & 3) * 64;
    const int cog = warp * 4;
    const int co_abs0 = cochunk * 32 + cog;

    int off[8];
#pragma unroll
    for (int i = 0; i < 8; ++i) {
        int px = lane + 32 * i;
        off[i] = (px >> 6) * 66 + (px & 63);
    }

    float acc[8][4];
#pragma unroll
    for (int j = 0; j < 4; ++j) {
        float bc = b_c2[co_abs0 + j];
#pragma unroll
        for (int i = 0; i < 8; ++i) acc[i][j] = bc;
    }

    for (int ci0 = 0; ci0 < 128; ci0 += 8) {
        __syncthreads();
        for (int e = tid; e < 32 * 8 * 9; e += 256) {
            int co_l = e / 72; int rem = e - co_l * 72;
            int ci_l = rem / 9; int k = rem - ci_l * 9;
            wct[(ci_l * 9 + k) * 33 + co_l] =
                w_c2[((size_t)(cochunk * 32 + co_l) * 128 + ci0 + ci_l) * 9 + k];
        }
        for (int e = tid; e < 8 * 6 * 66; e += 256) {
            int ci_l = e / 396; int rem = e - ci_l * 396;
            int rr = rem / 66; int cc = rem - rr * 66;
            int row = h0 + rr - 1; row = row < 0 ? 0 : (row > 255 ? 255 : row);
            int col = w0 + cc - 1; col = col < 0 ? 0 : (col > 255 ? 255 : col);
            yt[ci_l * 396 + rr * 66 + cc] =
                g_y1[((size_t)(b * CC + ci0 + ci_l)) * HW + row * WWD + col];
        }
        __syncthreads();
        for (int ci = 0; ci < 8; ++ci) {
            int yb = ci * 396;
            int wb = ci * 297 + cog;
#pragma unroll
            for (int k = 0; k < 9; ++k) {
                float wv0 = wct[wb + k * 33];
                float wv1 = wct[wb + k * 33 + 1];
                float wv2 = wct[wb + k * 33 + 2];
                float wv3 = wct[wb + k * 33 + 3];
                int tko = (k / 3) * 66 + (k % 3);
#pragma unroll
                for (int i = 0; i < 8; ++i) {
                    float yv = yt[yb + off[i] + tko];
                    acc[i][0] += yv * wv0; acc[i][1] += yv * wv1;
                    acc[i][2] += yv * wv2; acc[i][3] += yv * wv3;
                }
            }
        }
    }
#pragma unroll
    for (int j = 0; j < 4; ++j) {
        int co = co_abs0 + j;
        size_t base = ((size_t)(b * CC + co)) * HW;
#pragma unroll
        for (int i = 0; i < 8; ++i) {
            int px = lane + 32 * i;
            size_t a = base + (size_t)(h0 + (px >> 6)) * WWD + w0 + (px & 63);
            float v = acc[i][j];
            v = v > 0.f ? v : 0.1f * v;
            out[a] = g_x2[a] + v;
        }
    }
}

// ---------------------------------------------------------------------------
extern "C" void kernel_launch(void* const* d_in, const int* in_sizes, int n_in,
                              void* d_out, int out_size) {
    const float* x      = (const float*)d_in[0];
    const float* delta  = (const float*)d_in[1];
    const int*   index  = (const int*)d_in[2];
    const float* w_qkv  = (const float*)d_in[3];
    const float* b_qkv  = (const float*)d_in[4];
    const float* w_head = (const float*)d_in[5];
    const float* b_head = (const float*)d_in[6];
    const float* w_b1   = (const float*)d_in[7];
    const float* b_b1   = (const float*)d_in[8];
    const float* w_b2   = (const float*)d_in[9];
    const float* b_b2   = (const float*)d_in[10];
    const float* w_c1   = (const float*)d_in[11];
    const float* b_c1   = (const float*)d_in[12];
    const float* w_c2   = (const float*)d_in[13];
    const float* b_c2   = (const float*)d_in[14];
    float* out = (float*)d_out;

    const int attn_smem = (64 * XW_S + 64 * QKV_S + 128 * WT_S) * 4;  // 199,680 B
    const int c1_smem   = (128 * 65 + 128 * WT_S) * 4;                // 101,376 B
    cudaFuncSetAttribute(k_attn,  cudaFuncAttributeMaxDynamicSharedMemorySize, attn_smem);
    cudaFuncSetAttribute(k_conv1, cudaFuncAttributeMaxDynamicSharedMemorySize, c1_smem);

    k_bias <<<16, 256>>>(delta, index, w_b1, b_b1, w_b2, b_b2);
    k_attn <<<4096, 256, attn_smem>>>(x, w_qkv, b_qkv, w_head, b_head);
    k_conv1<<<4096, 256, c1_smem>>>(w_c1, b_c1);
    k_conv2<<<4096, 256>>>(w_c2, b_c2, out);
}

// round 11
// speedup vs baseline: 1.4234x; 1.4234x over previous
#include <cuda_runtime.h>
#include <cuda_bf16.h>
#include <stdint.h>
#include <math.h>

// Problem constants
#define CC   128
#define HH   256
#define WWD  256
#define HW   65536
#define XW_S 129
#define QKV_S 385
#define WT_S 133

// conv2 mma tiling
#define CI_S 136          // padded ci stride (bf16 elems) -> 272B, conflict-free fragment LDS

// Scratch (device globals; no cudaMalloc allowed)
__device__ float g_bias[64 * 64];
__device__ float g_x2[4 * CC * HW];              // x + attention residual stream (NCHW fp32)
__device__ unsigned short g_yh[4 * HW * CC];     // gelu(conv1) hi, NHWC bf16
__device__ unsigned short g_yl[4 * HW * CC];     // gelu(conv1) lo, NHWC bf16
__device__ unsigned short g_w2pk[9 * 32768];     // conv2 weights per tap: [hi 128x128][lo 128x128] bf16 row-major co x ci

__device__ __forceinline__ float gelu_exact(float v) {
    return 0.5f * v * (1.0f + erff(v * 0.70710678118654752440f));
}

extern __shared__ float smem[];

__device__ __forceinline__ void mma_bf16(float* d, const uint32_t* a, const uint32_t* b) {
    asm volatile(
        "mma.sync.aligned.m16n8k16.row.col.f32.bf16.bf16.f32 "
        "{%0,%1,%2,%3}, {%4,%5,%6,%7}, {%8,%9}, {%0,%1,%2,%3};\n"
        : "+f"(d[0]), "+f"(d[1]), "+f"(d[2]), "+f"(d[3])
        : "r"(a[0]), "r"(a[1]), "r"(a[2]), "r"(a[3]), "r"(b[0]), "r"(b[1]));
}

// ---------------------------------------------------------------------------
// Kernel 0: relative-position bias MLP
// ---------------------------------------------------------------------------
__global__ void k_bias(const float* __restrict__ delta, const int* __restrict__ index,
                       const float* __restrict__ w_b1, const float* __restrict__ b_b1,
                       const float* __restrict__ w_b2, const float* __restrict__ b_b2) {
    int t = blockIdx.x * blockDim.x + threadIdx.x;
    if (t >= 4096) return;
    int u = index[t];
    float dx = delta[2 * u], dy = delta[2 * u + 1];
    float acc = b_b2[0];
#pragma unroll
    for (int j = 0; j < 16; ++j) {
        float h = dx * w_b1[2 * j] + dy * w_b1[2 * j + 1] + b_b1[j];
        acc += w_b2[j] * gelu_exact(h);
    }
    g_bias[t] = acc;
}

// ---------------------------------------------------------------------------
// Kernel 0b: pre-pack conv2 weights into per-tap bf16 hi/lo, row-major co x ci
// ---------------------------------------------------------------------------
__global__ void k_wpack(const float* __restrict__ w_c2) {
    int idx = blockIdx.x * blockDim.x + threadIdx.x;
    if (idx >= 9 * 128 * 128) return;
    int tap = idx / 16384;
    int r   = idx & 16383;
    int co  = r >> 7, ci = r & 127;
    float v = w_c2[(size_t)(co * 128 + ci) * 9 + tap];
    __nv_bfloat16 h = __float2bfloat16(v);
    __nv_bfloat16 l = __float2bfloat16(v - __bfloat162float(h));
    unsigned short* base = g_w2pk + tap * 32768;
    base[co * 128 + ci]         = *(unsigned short*)&h;
    base[16384 + co * 128 + ci] = *(unsigned short*)&l;
}

// ---------------------------------------------------------------------------
// Kernel 1: window attention (fp32 FFMA path). Writes g_x2 = x + attn.
// ---------------------------------------------------------------------------
__global__ void __launch_bounds__(256, 1)
k_attn(const float* __restrict__ x,
       const float* __restrict__ w_qkv, const float* __restrict__ b_qkv,
       const float* __restrict__ w_head, const float* __restrict__ b_head) {
    float* xw  = smem;
    float* qkv = smem + 64 * XW_S;
    float* wt  = qkv + 64 * QKV_S;

    const int tid = threadIdx.x;
    const int warp = tid >> 5, lane = tid & 31;
    const int wid = blockIdx.x;
    const int b   = wid >> 10;
    const int ohi = (wid >> 5) & 31;
    const int owi = wid & 31;
    const float* xptr = x + (size_t)b * CC * HW + ohi * 8 * WWD + owi * 8;
    const int n0 = warp * 8;

    for (int e = tid; e < 64 * 128; e += 256) {
        int c = e >> 6, n = e & 63;
        xw[n * XW_S + c] = xptr[(size_t)c * HW + (n >> 3) * WWD + (n & 7)];
    }

    for (int t3 = 0; t3 < 3; ++t3) {
        __syncthreads();
        for (int e = tid; e < 128 * 128; e += 256) {
            int c = e & 127, o = e >> 7;
            wt[c * WT_S + o] = w_qkv[(size_t)(t3 * 128 + o) * 128 + c];
        }
        __syncthreads();
        float acc[8][4];
#pragma unroll
        for (int j = 0; j < 4; ++j) {
            float bq = b_qkv[t3 * 128 + lane + 32 * j];
#pragma unroll
            for (int i = 0; i < 8; ++i) acc[i][j] = bq;
        }
        for (int c = 0; c < 128; ++c) {
            float w0 = wt[c * WT_S + lane];
            float w1 = wt[c * WT_S + lane + 32];
            float w2 = wt[c * WT_S + lane + 64];
            float w3 = wt[c * WT_S + lane + 96];
#pragma unroll
            for (int i = 0; i < 8; ++i) {
                float xv = xw[(n0 + i) * XW_S + c];
                acc[i][0] += xv * w0; acc[i][1] += xv * w1;
                acc[i][2] += xv * w2; acc[i][3] += xv * w3;
            }
        }
#pragma unroll
        for (int i = 0; i < 8; ++i)
#pragma unroll
            for (int j = 0; j < 4; ++j)
                qkv[(n0 + i) * QKV_S + t3 * 128 + lane + 32 * j] = acc[i][j];
    }
    __syncthreads();

    float* sc = wt;
    float* ao = xw;

    for (int h = 0; h < 2; ++h) {
        const int qo = h * 64, ko = 128 + h * 64, vo = 256 + h * 64;
        {
            float a0[8], a1[8];
#pragma unroll
            for (int i = 0; i < 8; ++i) { a0[i] = 0.f; a1[i] = 0.f; }
            for (int d = 0; d < 64; ++d) {
                float k0 = qkv[lane * QKV_S + ko + d];
                float k1 = qkv[(lane + 32) * QKV_S + ko + d];
#pragma unroll
                for (int i = 0; i < 8; ++i) {
                    float qv = qkv[(n0 + i) * QKV_S + qo + d];
                    a0[i] += qv * k0; a1[i] += qv * k1;
                }
            }
#pragma unroll
            for (int i = 0; i < 8; ++i) {
                int n = n0 + i;
                sc[n * 66 + lane]      = a0[i] * 0.125f + g_bias[n * 64 + lane];
                sc[n * 66 + lane + 32] = a1[i] * 0.125f + g_bias[n * 64 + lane + 32];
            }
        }
        __syncthreads();
        {
            int row = tid >> 2, sub = tid & 3;
            float* r = sc + row * 66 + sub * 16;
            float v[16];
            float mx = -1e30f;
#pragma unroll
            for (int m = 0; m < 16; ++m) { v[m] = r[m]; mx = fmaxf(mx, v[m]); }
            mx = fmaxf(mx, __shfl_xor_sync(0xffffffffu, mx, 1));
            mx = fmaxf(mx, __shfl_xor_sync(0xffffffffu, mx, 2));
            float s = 0.f;
#pragma unroll
            for (int m = 0; m < 16; ++m) { v[m] = __expf(v[m] - mx); s += v[m]; }
            s += __shfl_xor_sync(0xffffffffu, s, 1);
            s += __shfl_xor_sync(0xffffffffu, s, 2);
            float inv = 1.f / s;
#pragma unroll
            for (int m = 0; m < 16; ++m) r[m] = v[m] * inv;
        }
        __syncthreads();
        {
            float a0[8], a1[8];
#pragma unroll
            for (int i = 0; i < 8; ++i) { a0[i] = 0.f; a1[i] = 0.f; }
            for (int m = 0; m < 64; ++m) {
                float v0 = qkv[m * QKV_S + vo + lane];
                float v1 = qkv[m * QKV_S + vo + lane + 32];
#pragma unroll
                for (int i = 0; i < 8; ++i) {
                    float p = sc[(n0 + i) * 66 + m];
                    a0[i] += p * v0; a1[i] += p * v1;
                }
            }
#pragma unroll
            for (int i = 0; i < 8; ++i) {
                ao[(n0 + i) * XW_S + h * 64 + lane]      = a0[i];
                ao[(n0 + i) * XW_S + h * 64 + lane + 32] = a1[i];
            }
        }
        __syncthreads();
    }

    for (int e = tid; e < 128 * 128; e += 256) {
        int cp = e & 127, c = e >> 7;
        wt[cp * WT_S + c] = w_head[(size_t)c * 128 + cp];
    }
    __syncthreads();
    float acc[8][4];
#pragma unroll
    for (int j = 0; j < 4; ++j) {
        float bh = b_head[lane + 32 * j];
#pragma unroll
        for (int i = 0; i < 8; ++i) acc[i][j] = bh;
    }
    for (int cp = 0; cp < 128; ++cp) {
        float w0 = wt[cp * WT_S + lane];
        float w1 = wt[cp * WT_S + lane + 32];
        float w2 = wt[cp * WT_S + lane + 64];
        float w3 = wt[cp * WT_S + lane + 96];
#pragma unroll
        for (int i = 0; i < 8; ++i) {
            float av = ao[(n0 + i) * XW_S + cp];
            acc[i][0] += av * w0; acc[i][1] += av * w1;
            acc[i][2] += av * w2; acc[i][3] += av * w3;
        }
    }
#pragma unroll
    for (int j = 0; j < 4; ++j) {
        int c = lane + 32 * j;
        const float* xrow = xptr + (size_t)c * HW + warp * WWD;
        float* orow = g_x2 + ((size_t)(b * CC + c)) * HW + (ohi * 8 + warp) * WWD + owi * 8;
#pragma unroll
        for (int i = 0; i < 8; ++i)
            orow[i] = acc[i][j] + xrow[i];
    }
}

// ---------------------------------------------------------------------------
// Kernel 2: 1x1 conv + exact GELU -> y_hi/y_lo bf16 NHWC.
// ---------------------------------------------------------------------------
__global__ void __launch_bounds__(256)
k_conv1(const float* __restrict__ w_c1, const float* __restrict__ b_c1) {
    float* xt  = smem;
    float* wct = smem + 128 * 65;
    const int tid = threadIdx.x, warp = tid >> 5, lane = tid & 31;
    const int pid0 = blockIdx.x * 64;
    const int b = pid0 >> 16;
    const int hw0 = pid0 & 65535;
    const float* xin = g_x2 + (size_t)b * CC * HW + hw0;

    for (int e = tid; e < 128 * 128; e += 256) {
        int ci = e & 127, co = e >> 7;
        wct[ci * WT_S + co] = w_c1[(size_t)co * 128 + ci];
    }
    for (int e = tid; e < 128 * 64; e += 256) {
        int ci = e >> 6, p = e & 63;
        xt[ci * 65 + p] = xin[(size_t)ci * HW + p];
    }
    __syncthreads();

    float acc[8][4];
#pragma unroll
    for (int j = 0; j < 4; ++j) {
        float bc = b_c1[lane + 32 * j];
#pragma unroll
        for (int i = 0; i < 8; ++i) acc[i][j] = bc;
    }
    const int p0 = warp * 8;
    for (int ci = 0; ci < 128; ++ci) {
        float w0 = wct[ci * WT_S + lane];
        float w1 = wct[ci * WT_S + lane + 32];
        float w2 = wct[ci * WT_S + lane + 64];
        float w3 = wct[ci * WT_S + lane + 96];
#pragma unroll
        for (int i = 0; i < 8; ++i) {
            float xv = xt[ci * 65 + p0 + i];
            acc[i][0] += xv * w0; acc[i][1] += xv * w1;
            acc[i][2] += xv * w2; acc[i][3] += xv * w3;
        }
    }
#pragma unroll
    for (int j = 0; j < 4; ++j) {
        int co = lane + 32 * j;
#pragma unroll
        for (int i = 0; i < 8; ++i) {
            float v = gelu_exact(acc[i][j]);
            __nv_bfloat16 h = __float2bfloat16(v);
            __nv_bfloat16 l = __float2bfloat16(v - __bfloat162float(h));
            size_t o = ((size_t)(b * 65536 + hw0 + p0 + i)) * 128 + co;
            g_yh[o] = *(unsigned short*)&h;
            g_yl[o] = *(unsigned short*)&l;
        }
    }
}

// ---------------------------------------------------------------------------
// Kernel 3: 3x3 conv via mma.sync bf16 hi/lo split (3 MMAs per product).
// Block = 128 co x (4 rows x 32 cols = 128 px). 2048 blocks, 256 threads.
// Halo y (6x34 px, hi+lo) staged once; per-tap weights staged per iteration.
// Warp w: co chunk (w&3)*32 (M=32), rowpair (w>>2) (N=64 px = 2 rows x 32).
// smem: [w hi|lo: 2*128*CI_S*2 = 69,632][yH 204*CI_S*2 = 55,488][yL 55,488]
// ---------------------------------------------------------------------------
__global__ void __launch_bounds__(256, 1)
k_conv2(const float* __restrict__ b_c2, float* __restrict__ out) {
    unsigned short* wS = (unsigned short*)smem;            // [2][128][CI_S]
    unsigned short* yH = wS + 2 * 128 * CI_S;              // [204][CI_S]
    unsigned short* yL = yH + 204 * CI_S;                  // [204][CI_S]

    const int tid = threadIdx.x, warp = tid >> 5, lane = tid & 31;
    const int gid = lane >> 2, tig = lane & 3;
    const int c0 = (blockIdx.x & 7) * 32;
    const int r0 = ((blockIdx.x >> 3) & 63) * 4;
    const int b  = blockIdx.x >> 9;
    const int wq = warp & 3;          // co chunk
    const int rp = warp >> 2;         // rowpair

    // ---- stage halo y tile (hi+lo), 6 rows x 34 cols, edge-clamped ----
    for (int e = tid; e < 204 * 16; e += 256) {
        int px = e >> 4, c16 = e & 15;
        int hr = px / 34, hc = px - hr * 34;
        int r = r0 + hr - 1; r = r < 0 ? 0 : (r > 255 ? 255 : r);
        int c = c0 + hc - 1; c = c < 0 ? 0 : (c > 255 ? 255 : c);
        size_t src = ((size_t)(b * 65536 + r * 256 + c)) * 128 + c16 * 8;
        int dst = px * CI_S + c16 * 8;
        *(uint4*)(yH + dst) = *(const uint4*)(g_yh + src);
        *(uint4*)(yL + dst) = *(const uint4*)(g_yl + src);
    }

    float acc[2][8][4];
#pragma unroll
    for (int mi = 0; mi < 2; ++mi)
#pragma unroll
        for (int nf = 0; nf < 8; ++nf)
#pragma unroll
            for (int q = 0; q < 4; ++q) acc[mi][nf][q] = 0.f;

    for (int tap = 0; tap < 9; ++tap) {
        const int ky = tap / 3, kx = tap - ky * 3;
        __syncthreads();
        // stage per-tap weights hi+lo into padded smem
        {
            const unsigned short* src = g_w2pk + tap * 32768;
            for (int e = tid; e < 128 * 16; e += 256) {
                int co = e >> 4, c16 = e & 15;
                int dst = co * CI_S + c16 * 8;
                *(uint4*)(wS + dst)               = *(const uint4*)(src + co * 128 + c16 * 8);
                *(uint4*)(wS + 128 * CI_S + dst)  = *(const uint4*)(src + 16384 + co * 128 + c16 * 8);
            }
        }
        __syncthreads();

        // halo px base for each of this warp's 8 N-fragment groups
        int hb[8];
#pragma unroll
        for (int nf = 0; nf < 8; ++nf) {
            int rip = nf >> 2, colb = (nf & 3) * 8;
            hb[nf] = ((rp * 2 + rip + ky) * 34 + colb + gid + kx) * CI_S;
        }

#pragma unroll
        for (int s = 0; s < 3; ++s) {
            const unsigned short* Aw = wS + ((s == 1) ? 128 * CI_S : 0);
            const unsigned short* By = (s == 2) ? yL : yH;
#pragma unroll
            for (int kk = 0; kk < 8; ++kk) {
                const int k0 = kk * 16 + 2 * tig;
                uint32_t a[2][4], bb[8][2];
#pragma unroll
                for (int mi = 0; mi < 2; ++mi) {
                    const unsigned short* ap = Aw + (wq * 32 + mi * 16 + gid) * CI_S + k0;
                    a[mi][0] = *(const uint32_t*)(ap);
                    a[mi][1] = *(const uint32_t*)(ap + 8 * CI_S);
                    a[mi][2] = *(const uint32_t*)(ap + 8);
                    a[mi][3] = *(const uint32_t*)(ap + 8 * CI_S + 8);
                }
#pragma unroll
                for (int nf = 0; nf < 8; ++nf) {
                    const unsigned short* bp = By + hb[nf] + k0;
                    bb[nf][0] = *(const uint32_t*)(bp);
                    bb[nf][1] = *(const uint32_t*)(bp + 8);
                }
#pragma unroll
                for (int mi = 0; mi < 2; ++mi)
#pragma unroll
                    for (int nf = 0; nf < 8; ++nf)
                        mma_bf16(acc[mi][nf], a[mi], bb[nf]);
            }
        }
    }

    // ---- epilogue: bias + LeakyReLU + residual -> out (NCHW) ----
#pragma unroll
    for (int mi = 0; mi < 2; ++mi) {
        const int co_lo = wq * 32 + mi * 16 + gid;
        const int co_hi = co_lo + 8;
        const float bl = b_c2[c0 * 0 + co_lo];   // (bias indexed by co only)
        const float bh2 = b_c2[co_hi];
#pragma unroll
        for (int nf = 0; nf < 8; ++nf) {
            int rip = nf >> 2;
            int col = c0 + (nf & 3) * 8 + 2 * tig;
            int row = r0 + rp * 2 + rip;
            size_t pbase = (size_t)(b * 65536 + row * 256 + col);
            {
                size_t adr = ((size_t)co_lo) * 262144 + ((size_t)b * 128) * 0 + ((size_t)(b * 128 + co_lo)) * 65536 + (size_t)row * 256 + col;
                // recompute cleanly:
                adr = ((size_t)(b * 128 + co_lo)) * 65536 + (size_t)row * 256 + col;
                float2 res = *(const float2*)(g_x2 + adr);
                float v0 = acc[mi][nf][0] + bl;
                float v1 = acc[mi][nf][1] + bl;
                v0 = v0 > 0.f ? v0 : 0.1f * v0;
                v1 = v1 > 0.f ? v1 : 0.1f * v1;
                float2 o; o.x = res.x + v0; o.y = res.y + v1;
                *(float2*)(out + adr) = o;
            }
            {
                size_t adr = ((size_t)(b * 128 + co_hi)) * 65536 + (size_t)row * 256 + col;
                float2 res = *(const float2*)(g_x2 + adr);
                float v2 = acc[mi][nf][2] + bh2;
                float v3 = acc[mi][nf][3] + bh2;
                v2 = v2 > 0.f ? v2 : 0.1f * v2;
                v3 = v3 > 0.f ? v3 : 0.1f * v3;
                float2 o; o.x = res.x + v2; o.y = res.y + v3;
                *(float2*)(out + adr) = o;
            }
            (void)pbase;
        }
    }
}

// ---------------------------------------------------------------------------
extern "C" void kernel_launch(void* const* d_in, const int* in_sizes, int n_in,
                              void* d_out, int out_size) {
    const float* x      = (const float*)d_in[0];
    const float* delta  = (const float*)d_in[1];
    const int*   index  = (const int*)d_in[2];
    const float* w_qkv  = (const float*)d_in[3];
    const float* b_qkv  = (const float*)d_in[4];
    const float* w_head = (const float*)d_in[5];
    const float* b_head = (const float*)d_in[6];
    const float* w_b1   = (const float*)d_in[7];
    const float* b_b1   = (const float*)d_in[8];
    const float* w_b2   = (const float*)d_in[9];
    const float* b_b2   = (const float*)d_in[10];
    const float* w_c1   = (const float*)d_in[11];
    const float* b_c1   = (const float*)d_in[12];
    const float* w_c2   = (const float*)d_in[13];
    const float* b_c2   = (const float*)d_in[14];
    float* out = (float*)d_out;

    const int attn_smem = (64 * XW_S + 64 * QKV_S + 128 * WT_S) * 4;  // 199,680 B
    const int c1_smem   = (128 * 65 + 128 * WT_S) * 4;                // 101,376 B
    const int c2_smem   = (2 * 128 * CI_S + 2 * 204 * CI_S) * 2;      // 180,608 B
    cudaFuncSetAttribute(k_attn,  cudaFuncAttributeMaxDynamicSharedMemorySize, attn_smem);
    cudaFuncSetAttribute(k_conv1, cudaFuncAttributeMaxDynamicSharedMemorySize, c1_smem);
    cudaFuncSetAttribute(k_conv2, cudaFuncAttributeMaxDynamicSharedMemorySize, c2_smem);

    k_bias <<<16, 256>>>(delta, index, w_b1, b_b1, w_b2, b_b2);
    k_wpack<<<576, 256>>>(w_c2);
    k_attn <<<4096, 256, attn_smem>>>(x, w_qkv, b_qkv, w_head, b_head);
    k_conv1<<<4096, 256, c1_smem>>>(w_c1, b_c1);
    k_conv2<<<2048, 256, c2_smem>>>(b_c2, out);
}

// round 12
// speedup vs baseline: 2.3305x; 1.6372x over previous
#include <cuda_runtime.h>
#include <cuda_bf16.h>
#include <stdint.h>
#include <math.h>

// Problem constants
#define CC   128
#define HW   65536
#define CI_S 136          // padded k-stride (bf16 elems) -> conflict-free fragment LDS

// Scratch (device globals; no cudaMalloc allowed)
__device__ float g_bias[64 * 64];
__device__ float g_x2[4 * CC * HW];              // x + attention residual (NCHW fp32)
__device__ unsigned short g_x2h[4 * HW * CC];    // x2 hi, NHWC bf16
__device__ unsigned short g_x2l[4 * HW * CC];    // x2 lo, NHWC bf16
__device__ unsigned short g_yh[4 * HW * CC];     // gelu(conv1) hi, NHWC bf16
__device__ unsigned short g_yl[4 * HW * CC];     // gelu(conv1) lo, NHWC bf16
__device__ unsigned short g_w2pk[9 * 32768];     // conv2 w per tap: [hi 128x128][lo] co x ci
__device__ unsigned short g_lwh[640 * 128];      // rows 0-383 w_qkv, 384-511 w_head, 512-639 w_c1 (hi)
__device__ unsigned short g_lwl[640 * 128];      // same (lo)

__device__ __forceinline__ float gelu_exact(float v) {
    return 0.5f * v * (1.0f + erff(v * 0.70710678118654752440f));
}

extern __shared__ float smem[];

__device__ __forceinline__ void mma_bf16(float* d, const uint32_t* a, const uint32_t* b) {
    asm volatile(
        "mma.sync.aligned.m16n8k16.row.col.f32.bf16.bf16.f32 "
        "{%0,%1,%2,%3}, {%4,%5,%6,%7}, {%8,%9}, {%0,%1,%2,%3};\n"
        : "+f"(d[0]), "+f"(d[1]), "+f"(d[2]), "+f"(d[3])
        : "r"(a[0]), "r"(a[1]), "r"(a[2]), "r"(a[3]), "r"(b[0]), "r"(b[1]));
}

// one m16-row k16-step against 8 n-frags, 3-term hi/lo split, shared loads.
// ah_p/al_p pre-offset: A + row*astr + k0 + 2*tig ; bh_p/bl_p: B + (n0+g)*bstr + k0 + 2*tig
__device__ __forceinline__ void mma3_8(
    float (*acc)[4],
    const unsigned short* ah_p, const unsigned short* al_p, const int astr,
    const unsigned short* bh_p, const unsigned short* bl_p, const int bstr)
{
    uint32_t aH[4], aL[4], bb[8][2];
    aH[0] = *(const uint32_t*)(ah_p);
    aH[1] = *(const uint32_t*)(ah_p + 8 * astr);
    aH[2] = *(const uint32_t*)(ah_p + 8);
    aH[3] = *(const uint32_t*)(ah_p + 8 * astr + 8);
    aL[0] = *(const uint32_t*)(al_p);
    aL[1] = *(const uint32_t*)(al_p + 8 * astr);
    aL[2] = *(const uint32_t*)(al_p + 8);
    aL[3] = *(const uint32_t*)(al_p + 8 * astr + 8);
#pragma unroll
    for (int nf = 0; nf < 8; ++nf) {
        const unsigned short* bp = bh_p + nf * 8 * bstr;
        bb[nf][0] = *(const uint32_t*)(bp);
        bb[nf][1] = *(const uint32_t*)(bp + 8);
    }
#pragma unroll
    for (int nf = 0; nf < 8; ++nf) mma_bf16(acc[nf], aH, bb[nf]);
#pragma unroll
    for (int nf = 0; nf < 8; ++nf) mma_bf16(acc[nf], aL, bb[nf]);
#pragma unroll
    for (int nf = 0; nf < 8; ++nf) {
        const unsigned short* bp = bl_p + nf * 8 * bstr;
        bb[nf][0] = *(const uint32_t*)(bp);
        bb[nf][1] = *(const uint32_t*)(bp + 8);
    }
#pragma unroll
    for (int nf = 0; nf < 8; ++nf) mma_bf16(acc[nf], aH, bb[nf]);
}

// pack pair (v0,v1) into bf16x2 hi word + lo word
__device__ __forceinline__ uint32_t pkhl(float v0, float v1, uint32_t& lo) {
    __nv_bfloat16 h0 = __float2bfloat16(v0), h1 = __float2bfloat16(v1);
    __nv_bfloat16 l0 = __float2bfloat16(v0 - __bfloat162float(h0));
    __nv_bfloat16 l1 = __float2bfloat16(v1 - __bfloat162float(h1));
    lo = ((uint32_t)(*(unsigned short*)&l1) << 16) | (*(unsigned short*)&l0);
    return ((uint32_t)(*(unsigned short*)&h1) << 16) | (*(unsigned short*)&h0);
}
__device__ __forceinline__ void hl1(float v, unsigned short& h, unsigned short& l) {
    __nv_bfloat16 hb = __float2bfloat16(v);
    __nv_bfloat16 lb = __float2bfloat16(v - __bfloat162float(hb));
    h = *(unsigned short*)&hb; l = *(unsigned short*)&lb;
}

// ---------------------------------------------------------------------------
// Kernel 0: relative-position bias MLP
// ---------------------------------------------------------------------------
__global__ void k_bias(const float* __restrict__ delta, const int* __restrict__ index,
                       const float* __restrict__ w_b1, const float* __restrict__ b_b1,
                       const float* __restrict__ w_b2, const float* __restrict__ b_b2) {
    int t = blockIdx.x * blockDim.x + threadIdx.x;
    if (t >= 4096) return;
    int u = index[t];
    float dx = delta[2 * u], dy = delta[2 * u + 1];
    float acc = b_b2[0];
#pragma unroll
    for (int j = 0; j < 16; ++j) {
        float h = dx * w_b1[2 * j] + dy * w_b1[2 * j + 1] + b_b1[j];
        acc += w_b2[j] * gelu_exact(h);
    }
    g_bias[t] = acc;
}

// ---------------------------------------------------------------------------
// Kernel 0b: pre-pack conv2 weights per-tap hi/lo (row-major co x ci)
// ---------------------------------------------------------------------------
__global__ void k_wpack(const float* __restrict__ w_c2) {
    int idx = blockIdx.x * blockDim.x + threadIdx.x;
    if (idx >= 9 * 128 * 128) return;
    int tap = idx / 16384;
    int r   = idx & 16383;
    int co  = r >> 7, ci = r & 127;
    float v = w_c2[(size_t)(co * 128 + ci) * 9 + tap];
    unsigned short h, l; hl1(v, h, l);
    unsigned short* base = g_w2pk + tap * 32768;
    base[co * 128 + ci]         = h;
    base[16384 + co * 128 + ci] = l;
}

// ---------------------------------------------------------------------------
// Kernel 0c: pre-pack linear weights (w_qkv | w_head | w_c1) hi/lo
// ---------------------------------------------------------------------------
__global__ void k_wpackL(const float* __restrict__ w_qkv, const float* __restrict__ w_head,
                         const float* __restrict__ w_c1) {
    int idx = blockIdx.x * blockDim.x + threadIdx.x;
    if (idx >= 640 * 128) return;
    int row = idx >> 7, ci = idx & 127;
    float v = (row < 384) ? w_qkv[idx]
            : (row < 512) ? w_head[(row - 384) * 128 + ci]
                          : w_c1[(row - 512) * 128 + ci];
    unsigned short h, l; hl1(v, h, l);
    g_lwh[idx] = h; g_lwl[idx] = l;
}

// ---------------------------------------------------------------------------
// Kernel 1: window attention via mma.sync bf16 hi/lo. One block per window.
// smem (unsigned short elems):
//   XH 0       XL 8704      (x window [64][136], hi/lo; later used for residual)
//   QH 17408   QL 26112     (q [64][136]; later o)
//   KH 34816   KL 43520     (k [64][136])
//   VTH 52224  VTL 61440    (v transposed [128][72])
//   WB 70656               (weights [128][136] hi + lo = 34816 shorts)
//     attn-phase overlay: SC fp32 [2][64][66] @70656, PH @87552, PL @96768 [2][64][72]
// total 105984 shorts = 211968 B
// ---------------------------------------------------------------------------
__global__ void __launch_bounds__(256, 1)
k_attn(const float* __restrict__ x,
       const float* __restrict__ b_qkv, const float* __restrict__ b_head) {
    unsigned short* S = (unsigned short*)smem;
    unsigned short* XH = S;
    unsigned short* XL = S + 8704;
    unsigned short* QH = S + 17408;
    unsigned short* QL = S + 26112;
    unsigned short* KH = S + 34816;
    unsigned short* KL = S + 43520;
    unsigned short* VTH = S + 52224;
    unsigned short* VTL = S + 61440;
    unsigned short* WBH = S + 70656;
    unsigned short* WBL = S + 88064;
    float* SC = (float*)(S + 70656);
    unsigned short* PH = S + 87552;
    unsigned short* PL = S + 96768;

    const int tid = threadIdx.x;
    const int warp = tid >> 5, lane = tid & 31;
    const int g = lane >> 2, tig = lane & 3;
    const int wid = blockIdx.x;
    const int b   = wid >> 10;
    const int ohi = (wid >> 5) & 31;
    const int owi = wid & 31;
    const float* xptr = x + (size_t)b * CC * HW + ohi * 8 * 256 + owi * 8;

    // ---- P1: load x window [64 tok][128 ch], convert hi/lo ----
    for (int e = tid; e < 8192; e += 256) {
        int c = e >> 6, n = e & 63;
        float v = xptr[(size_t)c * HW + (n >> 3) * 256 + (n & 7)];
        unsigned short h, l; hl1(v, h, l);
        XH[n * CI_S + c] = h; XL[n * CI_S + c] = l;
    }

    const int m0 = (warp & 3) * 16;
    const int n0 = (warp >> 2) * 64;

    // ---- P2: qkv = x @ Wqkv^T + b, three 128-co chunks ----
    for (int cc = 0; cc < 3; ++cc) {
        __syncthreads();
        for (int e = tid; e < 2048; e += 256) {
            int n = e >> 4, c8 = e & 15;
            int dst = n * CI_S + c8 * 8;
            int src = (cc * 128 + n) * 128 + c8 * 8;
            *(uint4*)(WBH + dst) = *(const uint4*)(g_lwh + src);
            *(uint4*)(WBL + dst) = *(const uint4*)(g_lwl + src);
        }
        __syncthreads();
        float acc[8][4];
#pragma unroll
        for (int nf = 0; nf < 8; ++nf)
#pragma unroll
            for (int q = 0; q < 4; ++q) acc[nf][q] = 0.f;
#pragma unroll
        for (int ks = 0; ks < 8; ++ks) {
            int k0 = ks * 16 + 2 * tig;
            mma3_8(acc, XH + (m0 + g) * CI_S + k0, XL + (m0 + g) * CI_S + k0, CI_S,
                        WBH + (n0 + g) * CI_S + k0, WBL + (n0 + g) * CI_S + k0, CI_S);
        }
#pragma unroll
        for (int nf = 0; nf < 8; ++nf) {
            int col = n0 + nf * 8 + 2 * tig;
            float bq0 = b_qkv[cc * 128 + col], bq1 = b_qkv[cc * 128 + col + 1];
            int r0 = m0 + g, r1 = m0 + g + 8;
            float v00 = acc[nf][0] + bq0, v01 = acc[nf][1] + bq1;
            float v10 = acc[nf][2] + bq0, v11 = acc[nf][3] + bq1;
            if (cc == 0) {
                uint32_t lo, hi;
                hi = pkhl(v00, v01, lo); *(uint32_t*)(QH + r0 * CI_S + col) = hi; *(uint32_t*)(QL + r0 * CI_S + col) = lo;
                hi = pkhl(v10, v11, lo); *(uint32_t*)(QH + r1 * CI_S + col) = hi; *(uint32_t*)(QL + r1 * CI_S + col) = lo;
            } else if (cc == 1) {
                uint32_t lo, hi;
                hi = pkhl(v00, v01, lo); *(uint32_t*)(KH + r0 * CI_S + col) = hi; *(uint32_t*)(KL + r0 * CI_S + col) = lo;
                hi = pkhl(v10, v11, lo); *(uint32_t*)(KH + r1 * CI_S + col) = hi; *(uint32_t*)(KL + r1 * CI_S + col) = lo;
            } else {
                unsigned short h, l;
                hl1(v00, h, l); VTH[col * 72 + r0] = h; VTL[col * 72 + r0] = l;
                hl1(v01, h, l); VTH[(col + 1) * 72 + r0] = h; VTL[(col + 1) * 72 + r0] = l;
                hl1(v10, h, l); VTH[col * 72 + r1] = h; VTL[col * 72 + r1] = l;
                hl1(v11, h, l); VTH[(col + 1) * 72 + r1] = h; VTL[(col + 1) * 72 + r1] = l;
            }
        }
    }
    __syncthreads();

    // ---- P3: scores = qk^T * 0.125 + bias -> SC fp32 ----
    {
        const int hd = warp >> 2, mq = (warp & 3) * 16;
        float acc[8][4];
#pragma unroll
        for (int nf = 0; nf < 8; ++nf)
#pragma unroll
            for (int q = 0; q < 4; ++q) acc[nf][q] = 0.f;
#pragma unroll
        for (int ks = 0; ks < 4; ++ks) {
            int k0 = hd * 64 + ks * 16 + 2 * tig;
            mma3_8(acc, QH + (mq + g) * CI_S + k0, QL + (mq + g) * CI_S + k0, CI_S,
                        KH + g * CI_S + k0, KL + g * CI_S + k0, CI_S);
        }
        float* sc = SC + hd * 4224;
#pragma unroll
        for (int nf = 0; nf < 8; ++nf) {
            int col = nf * 8 + 2 * tig;
            int r0 = mq + g, r1 = mq + g + 8;
            sc[r0 * 66 + col]     = acc[nf][0] * 0.125f + g_bias[r0 * 64 + col];
            sc[r0 * 66 + col + 1] = acc[nf][1] * 0.125f + g_bias[r0 * 64 + col + 1];
            sc[r1 * 66 + col]     = acc[nf][2] * 0.125f + g_bias[r1 * 64 + col];
            sc[r1 * 66 + col + 1] = acc[nf][3] * 0.125f + g_bias[r1 * 64 + col + 1];
        }
    }
    __syncthreads();

    // ---- softmax (fp32) + convert probs to hi/lo bf16 ----
    {
        int rid = tid >> 1, hd = rid >> 6, row = rid & 63, sub = tid & 1;
        float* r = SC + hd * 4224 + row * 66 + sub * 32;
        float v[32];
        float mx = -1e30f;
#pragma unroll
        for (int m = 0; m < 32; ++m) { v[m] = r[m]; mx = fmaxf(mx, v[m]); }
        mx = fmaxf(mx, __shfl_xor_sync(0xffffffffu, mx, 1));
        float s = 0.f;
#pragma unroll
        for (int m = 0; m < 32; ++m) { v[m] = __expf(v[m] - mx); s += v[m]; }
        s += __shfl_xor_sync(0xffffffffu, s, 1);
        float inv = 1.f / s;
        int base = hd * 4608 + row * 72 + sub * 32;
#pragma unroll
        for (int m = 0; m < 32; m += 2) {
            uint32_t lo, hi = pkhl(v[m] * inv, v[m + 1] * inv, lo);
            *(uint32_t*)(PH + base + m) = hi;
            *(uint32_t*)(PL + base + m) = lo;
        }
    }
    __syncthreads();

    // ---- P4: o = p @ v -> write into Q region [tok][136] ----
    {
        const int hd = warp >> 2, mq = (warp & 3) * 16;
        float acc[8][4];
#pragma unroll
        for (int nf = 0; nf < 8; ++nf)
#pragma unroll
            for (int q = 0; q < 4; ++q) acc[nf][q] = 0.f;
#pragma unroll
        for (int ks = 0; ks < 4; ++ks) {
            int k0 = ks * 16 + 2 * tig;
            mma3_8(acc, PH + hd * 4608 + (mq + g) * 72 + k0, PL + hd * 4608 + (mq + g) * 72 + k0, 72,
                        VTH + (hd * 64 + g) * 72 + k0, VTL + (hd * 64 + g) * 72 + k0, 72);
        }
#pragma unroll
        for (int nf = 0; nf < 8; ++nf) {
            int col = hd * 64 + nf * 8 + 2 * tig;
            int r0 = mq + g, r1 = mq + g + 8;
            uint32_t lo, hi;
            hi = pkhl(acc[nf][0], acc[nf][1], lo);
            *(uint32_t*)(QH + r0 * CI_S + col) = hi; *(uint32_t*)(QL + r0 * CI_S + col) = lo;
            hi = pkhl(acc[nf][2], acc[nf][3], lo);
            *(uint32_t*)(QH + r1 * CI_S + col) = hi; *(uint32_t*)(QL + r1 * CI_S + col) = lo;
        }
    }
    __syncthreads();

    // ---- P5: head proj + residual -> g_x2 (fp32 NCHW) + g_x2h/l (bf16 NHWC) ----
    for (int e = tid; e < 2048; e += 256) {
        int n = e >> 4, c8 = e & 15;
        int dst = n * CI_S + c8 * 8;
        int src = (384 + n) * 128 + c8 * 8;
        *(uint4*)(WBH + dst) = *(const uint4*)(g_lwh + src);
        *(uint4*)(WBL + dst) = *(const uint4*)(g_lwl + src);
    }
    __syncthreads();
    {
        float acc[8][4];
#pragma unroll
        for (int nf = 0; nf < 8; ++nf)
#pragma unroll
            for (int q = 0; q < 4; ++q) acc[nf][q] = 0.f;
#pragma unroll
        for (int ks = 0; ks < 8; ++ks) {
            int k0 = ks * 16 + 2 * tig;
            mma3_8(acc, QH + (m0 + g) * CI_S + k0, QL + (m0 + g) * CI_S + k0, CI_S,
                        WBH + (n0 + g) * CI_S + k0, WBL + (n0 + g) * CI_S + k0, CI_S);
        }
#pragma unroll
        for (int nf = 0; nf < 8; ++nf) {
            int co = n0 + nf * 8 + 2 * tig;
            float bh0 = b_head[co], bh1 = b_head[co + 1];
#pragma unroll
            for (int half = 0; half < 2; ++half) {
                int tok = m0 + g + half * 8;
                int prow = ohi * 8 + (tok >> 3), pcol = owi * 8 + (tok & 7);
                uint32_t xh2 = *(const uint32_t*)(XH + tok * CI_S + co);
                uint32_t xl2 = *(const uint32_t*)(XL + tok * CI_S + co);
                float x0 = __uint_as_float(xh2 << 16) + __uint_as_float(xl2 << 16);
                float x1 = __uint_as_float(xh2 & 0xffff0000u) + __uint_as_float(xl2 & 0xffff0000u);
                float o0 = acc[nf][half * 2]     + bh0 + x0;
                float o1 = acc[nf][half * 2 + 1] + bh1 + x1;
                size_t pix = (size_t)(b * HW + prow * 256 + pcol);
                g_x2[((size_t)(b * 128 + co)) * HW + prow * 256 + pcol]     = o0;
                g_x2[((size_t)(b * 128 + co + 1)) * HW + prow * 256 + pcol] = o1;
                uint32_t lo, hi = pkhl(o0, o1, lo);
                *(uint32_t*)(g_x2h + pix * 128 + co) = hi;
                *(uint32_t*)(g_x2l + pix * 128 + co) = lo;
            }
        }
    }
}

// ---------------------------------------------------------------------------
// Kernel 2: 1x1 conv + exact GELU via mma.sync, NHWC in/out hi-lo bf16.
// Block = 128 px x 128 co. smem: WH 0, WL 17408, BH 34816, BL 52224 (shorts)
// ---------------------------------------------------------------------------
__global__ void __launch_bounds__(256, 1)
k_conv1(const float* __restrict__ b_c1) {
    unsigned short* S = (unsigned short*)smem;
    unsigned short* WH = S;
    unsigned short* WL = S + 17408;
    unsigned short* BHt = S + 34816;
    unsigned short* BLt = S + 52224;
    const int tid = threadIdx.x, warp = tid >> 5, lane = tid & 31;
    const int g = lane >> 2, tig = lane & 3;
    const size_t px0 = (size_t)blockIdx.x * 128;

    for (int e = tid; e < 2048; e += 256) {
        int n = e >> 4, c8 = e & 15;
        int dst = n * CI_S + c8 * 8;
        int src = (512 + n) * 128 + c8 * 8;
        *(uint4*)(WH + dst) = *(const uint4*)(g_lwh + src);
        *(uint4*)(WL + dst) = *(const uint4*)(g_lwl + src);
    }
    for (int e = tid; e < 2048; e += 256) {
        int p = e >> 4, c8 = e & 15;
        int dst = p * CI_S + c8 * 8;
        size_t src = (px0 + p) * 128 + c8 * 8;
        *(uint4*)(BHt + dst) = *(const uint4*)(g_x2h + src);
        *(uint4*)(BLt + dst) = *(const uint4*)(g_x2l + src);
    }
    __syncthreads();

    const int m0 = (warp & 3) * 32;     // px
    const int n0 = (warp >> 2) * 64;    // co
    float acc[2][8][4];
#pragma unroll
    for (int mi = 0; mi < 2; ++mi)
#pragma unroll
        for (int nf = 0; nf < 8; ++nf)
#pragma unroll
            for (int q = 0; q < 4; ++q) acc[mi][nf][q] = 0.f;

#pragma unroll
    for (int ks = 0; ks < 8; ++ks) {
        int k0 = ks * 16 + 2 * tig;
#pragma unroll
        for (int mi = 0; mi < 2; ++mi) {
            mma3_8(acc[mi], BHt + (m0 + mi * 16 + g) * CI_S + k0, BLt + (m0 + mi * 16 + g) * CI_S + k0, CI_S,
                            WH + (n0 + g) * CI_S + k0, WL + (n0 + g) * CI_S + k0, CI_S);
        }
    }

#pragma unroll
    for (int mi = 0; mi < 2; ++mi)
#pragma unroll
        for (int nf = 0; nf < 8; ++nf) {
            int co = n0 + nf * 8 + 2 * tig;
            float bc0 = b_c1[co], bc1 = b_c1[co + 1];
#pragma unroll
            for (int half = 0; half < 2; ++half) {
                size_t px = px0 + m0 + mi * 16 + g + half * 8;
                float v0 = gelu_exact(acc[mi][nf][half * 2] + bc0);
                float v1 = gelu_exact(acc[mi][nf][half * 2 + 1] + bc1);
                uint32_t lo, hi = pkhl(v0, v1, lo);
                *(uint32_t*)(g_yh + px * 128 + co) = hi;
                *(uint32_t*)(g_yl + px * 128 + co) = lo;
            }
        }
}

// ---------------------------------------------------------------------------
// Kernel 3: 3x3 conv via mma.sync bf16 hi/lo split (unchanged from R11).
// ---------------------------------------------------------------------------
__global__ void __launch_bounds__(256, 1)
k_conv2(const float* __restrict__ b_c2, float* __restrict__ out) {
    unsigned short* wS = (unsigned short*)smem;            // [2][128][CI_S]
    unsigned short* yH = wS + 2 * 128 * CI_S;              // [204][CI_S]
    unsigned short* yL = yH + 204 * CI_S;                  // [204][CI_S]

    const int tid = threadIdx.x, warp = tid >> 5, lane = tid & 31;
    const int gid = lane >> 2, tig = lane & 3;
    const int c0 = (blockIdx.x & 7) * 32;
    const int r0 = ((blockIdx.x >> 3) & 63) * 4;
    const int b  = blockIdx.x >> 9;
    const int wq = warp & 3;
    const int rp = warp >> 2;

    for (int e = tid; e < 204 * 16; e += 256) {
        int px = e >> 4, c16 = e & 15;
        int hr = px / 34, hc = px - hr * 34;
        int r = r0 + hr - 1; r = r < 0 ? 0 : (r > 255 ? 255 : r);
        int c = c0 + hc - 1; c = c < 0 ? 0 : (c > 255 ? 255 : c);
        size_t src = ((size_t)(b * 65536 + r * 256 + c)) * 128 + c16 * 8;
        int dst = px * CI_S + c16 * 8;
        *(uint4*)(yH + dst) = *(const uint4*)(g_yh + src);
        *(uint4*)(yL + dst) = *(const uint4*)(g_yl + src);
    }

    float acc[2][8][4];
#pragma unroll
    for (int mi = 0; mi < 2; ++mi)
#pragma unroll
        for (int nf = 0; nf < 8; ++nf)
#pragma unroll
            for (int q = 0; q < 4; ++q) acc[mi][nf][q] = 0.f;

    for (int tap = 0; tap < 9; ++tap) {
        const int ky = tap / 3, kx = tap - ky * 3;
        __syncthreads();
        {
            const unsigned short* src = g_w2pk + tap * 32768;
            for (int e = tid; e < 128 * 16; e += 256) {
                int co = e >> 4, c16 = e & 15;
                int dst = co * CI_S + c16 * 8;
                *(uint4*)(wS + dst)               = *(const uint4*)(src + co * 128 + c16 * 8);
                *(uint4*)(wS + 128 * CI_S + dst)  = *(const uint4*)(src + 16384 + co * 128 + c16 * 8);
            }
        }
        __syncthreads();

        int hb[8];
#pragma unroll
        for (int nf = 0; nf < 8; ++nf) {
            int rip = nf >> 2, colb = (nf & 3) * 8;
            hb[nf] = ((rp * 2 + rip + ky) * 34 + colb + gid + kx) * CI_S;
        }

#pragma unroll
        for (int s = 0; s < 3; ++s) {
            const unsigned short* Aw = wS + ((s == 1) ? 128 * CI_S : 0);
            const unsigned short* By = (s == 2) ? yL : yH;
#pragma unroll
            for (int kk = 0; kk < 8; ++kk) {
                const int k0 = kk * 16 + 2 * tig;
                uint32_t a[2][4], bb[8][2];
#pragma unroll
                for (int mi = 0; mi < 2; ++mi) {
                    const unsigned short* ap = Aw + (wq * 32 + mi * 16 + gid) * CI_S + k0;
                    a[mi][0] = *(const uint32_t*)(ap);
                    a[mi][1] = *(const uint32_t*)(ap + 8 * CI_S);
                    a[mi][2] = *(const uint32_t*)(ap + 8);
                    a[mi][3] = *(const uint32_t*)(ap + 8 * CI_S + 8);
                }
#pragma unroll
                for (int nf = 0; nf < 8; ++nf) {
                    const unsigned short* bp = By + hb[nf] + k0;
                    bb[nf][0] = *(const uint32_t*)(bp);
                    bb[nf][1] = *(const uint32_t*)(bp + 8);
                }
#pragma unroll
                for (int mi = 0; mi < 2; ++mi)
#pragma unroll
                    for (int nf = 0; nf < 8; ++nf)
                        mma_bf16(acc[mi][nf], a[mi], bb[nf]);
            }
        }
    }

#pragma unroll
    for (int mi = 0; mi < 2; ++mi) {
        const int co_lo = wq * 32 + mi * 16 + gid;
        const int co_hi = co_lo + 8;
        const float bl = b_c2[co_lo];
        const float bh2 = b_c2[co_hi];
#pragma unroll
        for (int nf = 0; nf < 8; ++nf) {
            int rip = nf >> 2;
            int col = c0 + (nf & 3) * 8 + 2 * tig;
            int row = r0 + rp * 2 + rip;
            {
                size_t adr = ((size_t)(b * 128 + co_lo)) * 65536 + (size_t)row * 256 + col;
                float2 res = *(const float2*)(g_x2 + adr);
                float v0 = acc[mi][nf][0] + bl;
                float v1 = acc[mi][nf][1] + bl;
                v0 = v0 > 0.f ? v0 : 0.1f * v0;
                v1 = v1 > 0.f ? v1 : 0.1f * v1;
                float2 o; o.x = res.x + v0; o.y = res.y + v1;
                *(float2*)(out + adr) = o;
            }
            {
                size_t adr = ((size_t)(b * 128 + co_hi)) * 65536 + (size_t)row * 256 + col;
                float2 res = *(const float2*)(g_x2 + adr);
                float v2 = acc[mi][nf][2] + bh2;
                float v3 = acc[mi][nf][3] + bh2;
                v2 = v2 > 0.f ? v2 : 0.1f * v2;
                v3 = v3 > 0.f ? v3 : 0.1f * v3;
                float2 o; o.x = res.x + v2; o.y = res.y + v3;
                *(float2*)(out + adr) = o;
            }
        }
    }
}

// ---------------------------------------------------------------------------
extern "C" void kernel_launch(void* const* d_in, const int* in_sizes, int n_in,
                              void* d_out, int out_size) {
    const float* x      = (const float*)d_in[0];
    const float* delta  = (const float*)d_in[1];
    const int*   index  = (const int*)d_in[2];
    const float* w_qkv  = (const float*)d_in[3];
    const float* b_qkv  = (const float*)d_in[4];
    const float* w_head = (const float*)d_in[5];
    const float* b_head = (const float*)d_in[6];
    const float* w_b1   = (const float*)d_in[7];
    const float* b_b1   = (const float*)d_in[8];
    const float* w_b2   = (const float*)d_in[9];
    const float* b_b2   = (const float*)d_in[10];
    const float* w_c1   = (const float*)d_in[11];
    const float* b_c1   = (const float*)d_in[12];
    const float* w_c2   = (const float*)d_in[13];
    const float* b_c2   = (const float*)d_in[14];
    float* out = (float*)d_out;

    const int attn_smem = 105984 * 2;                 // 211,968 B
    const int c1_smem   = 69632 * 2;                  // 139,264 B
    const int c2_smem   = (2 * 128 * CI_S + 2 * 204 * CI_S) * 2;  // 180,608 B
    cudaFuncSetAttribute(k_attn,  cudaFuncAttributeMaxDynamicSharedMemorySize, attn_smem);
    cudaFuncSetAttribute(k_conv1, cudaFuncAttributeMaxDynamicSharedMemorySize, c1_smem);
    cudaFuncSetAttribute(k_conv2, cudaFuncAttributeMaxDynamicSharedMemorySize, c2_smem);

    k_bias  <<<16, 256>>>(delta, index, w_b1, b_b1, w_b2, b_b2);
    k_wpack <<<576, 256>>>(w_c2);
    k_wpackL<<<320, 256>>>(w_qkv, w_head, w_c1);
    k_attn  <<<4096, 256, attn_smem>>>(x, b_qkv, b_head);
    k_conv1 <<<2048, 256, c1_smem>>>(b_c1);
    k_conv2 <<<2048, 256, c2_smem>>>(b_c2, out);
}

// round 13
// speedup vs baseline: 3.1100x; 1.3345x over previous
#include <cuda_runtime.h>
#include <cuda_bf16.h>
#include <stdint.h>
#include <math.h>

// Problem constants
#define CC   128
#define HW   65536
#define CI_S 136          // padded k-stride (bf16 elems) -> conflict-free fragment LDS

// Scratch (device globals; no cudaMalloc allowed)
__device__ float g_bias[64 * 64];
__device__ float g_x2[4 * CC * HW];              // x + attention residual (NCHW fp32)
__device__ unsigned short g_x2h[4 * HW * CC];    // x2 hi, NHWC bf16
__device__ unsigned short g_x2l[4 * HW * CC];    // x2 lo, NHWC bf16
__device__ unsigned short g_yh[4 * HW * CC];     // gelu(conv1) hi, NHWC bf16
__device__ unsigned short g_yl[4 * HW * CC];     // gelu(conv1) lo, NHWC bf16
__device__ unsigned short g_w2pk[9 * 32768];     // conv2 w per tap: [hi 128x128][lo] co x ci
__device__ unsigned short g_lwh[640 * 128];      // rows 0-383 w_qkv, 384-511 w_head, 512-639 w_c1 (hi)
__device__ unsigned short g_lwl[640 * 128];      // same (lo)

__device__ __forceinline__ float gelu_exact(float v) {
    return 0.5f * v * (1.0f + erff(v * 0.70710678118654752440f));
}

extern __shared__ float smem[];

__device__ __forceinline__ uint32_t smem_u32(const void* p) {
    uint32_t a;
    asm("{ .reg .u64 t; cvta.to.shared.u64 t, %1; cvt.u32.u64 %0, t; }" : "=r"(a) : "l"(p));
    return a;
}

#define CP16(d, s) asm volatile("cp.async.cg.shared.global [%0], [%1], 16;\n" :: "r"(d), "l"(s))
#define CPCOMMIT() asm volatile("cp.async.commit_group;\n" ::: "memory")
#define CPWAIT1()  asm volatile("cp.async.wait_group 1;\n" ::: "memory")

__device__ __forceinline__ void mma_bf16(float* d, const uint32_t* a, const uint32_t* b) {
    asm volatile(
        "mma.sync.aligned.m16n8k16.row.col.f32.bf16.bf16.f32 "
        "{%0,%1,%2,%3}, {%4,%5,%6,%7}, {%8,%9}, {%0,%1,%2,%3};\n"
        : "+f"(d[0]), "+f"(d[1]), "+f"(d[2]), "+f"(d[3])
        : "r"(a[0]), "r"(a[1]), "r"(a[2]), "r"(a[3]), "r"(b[0]), "r"(b[1]));
}

// plain bf16: one m16 k16 step against 8 n-frags
__device__ __forceinline__ void mma1_8(float (*acc)[4],
    const unsigned short* a_p, const int astr,
    const unsigned short* b_p, const int bstr)
{
    uint32_t a[4], bb[2];
    a[0] = *(const uint32_t*)(a_p);
    a[1] = *(const uint32_t*)(a_p + 8 * astr);
    a[2] = *(const uint32_t*)(a_p + 8);
    a[3] = *(const uint32_t*)(a_p + 8 * astr + 8);
#pragma unroll
    for (int nf = 0; nf < 8; ++nf) {
        const unsigned short* bp = b_p + nf * 8 * bstr;
        bb[0] = *(const uint32_t*)(bp);
        bb[1] = *(const uint32_t*)(bp + 8);
        mma_bf16(acc[nf], a, bb);
    }
}

// 3-term hi/lo split (for conv path, where errors are not damped)
__device__ __forceinline__ void mma3_8(
    float (*acc)[4],
    const unsigned short* ah_p, const unsigned short* al_p, const int astr,
    const unsigned short* bh_p, const unsigned short* bl_p, const int bstr)
{
    uint32_t aH[4], aL[4], bb[8][2];
    aH[0] = *(const uint32_t*)(ah_p);
    aH[1] = *(const uint32_t*)(ah_p + 8 * astr);
    aH[2] = *(const uint32_t*)(ah_p + 8);
    aH[3] = *(const uint32_t*)(ah_p + 8 * astr + 8);
    aL[0] = *(const uint32_t*)(al_p);
    aL[1] = *(const uint32_t*)(al_p + 8 * astr);
    aL[2] = *(const uint32_t*)(al_p + 8);
    aL[3] = *(const uint32_t*)(al_p + 8 * astr + 8);
#pragma unroll
    for (int nf = 0; nf < 8; ++nf) {
        const unsigned short* bp = bh_p + nf * 8 * bstr;
        bb[nf][0] = *(const uint32_t*)(bp);
        bb[nf][1] = *(const uint32_t*)(bp + 8);
    }
#pragma unroll
    for (int nf = 0; nf < 8; ++nf) mma_bf16(acc[nf], aH, bb[nf]);
#pragma unroll
    for (int nf = 0; nf < 8; ++nf) mma_bf16(acc[nf], aL, bb[nf]);
#pragma unroll
    for (int nf = 0; nf < 8; ++nf) {
        const unsigned short* bp = bl_p + nf * 8 * bstr;
        bb[nf][0] = *(const uint32_t*)(bp);
        bb[nf][1] = *(const uint32_t*)(bp + 8);
    }
#pragma unroll
    for (int nf = 0; nf < 8; ++nf) mma_bf16(acc[nf], aH, bb[nf]);
}

__device__ __forceinline__ uint32_t pkhl(float v0, float v1, uint32_t& lo) {
    __nv_bfloat16 h0 = __float2bfloat16(v0), h1 = __float2bfloat16(v1);
    __nv_bfloat16 l0 = __float2bfloat16(v0 - __bfloat162float(h0));
    __nv_bfloat16 l1 = __float2bfloat16(v1 - __bfloat162float(h1));
    lo = ((uint32_t)(*(unsigned short*)&l1) << 16) | (*(unsigned short*)&l0);
    return ((uint32_t)(*(unsigned short*)&h1) << 16) | (*(unsigned short*)&h0);
}
__device__ __forceinline__ void hl1(float v, unsigned short& h, unsigned short& l) {
    __nv_bfloat16 hb = __float2bfloat16(v);
    __nv_bfloat16 lb = __float2bfloat16(v - __bfloat162float(hb));
    h = *(unsigned short*)&hb; l = *(unsigned short*)&lb;
}
__device__ __forceinline__ unsigned short bf1(float v) {
    __nv_bfloat16 hb = __float2bfloat16(v);
    return *(unsigned short*)&hb;
}
__device__ __forceinline__ uint32_t pk1(float v0, float v1) {
    __nv_bfloat16 h0 = __float2bfloat16(v0), h1 = __float2bfloat16(v1);
    return ((uint32_t)(*(unsigned short*)&h1) << 16) | (*(unsigned short*)&h0);
}

// ---------------------------------------------------------------------------
// Kernel 0: relative-position bias MLP
// ---------------------------------------------------------------------------
__global__ void k_bias(const float* __restrict__ delta, const int* __restrict__ index,
                       const float* __restrict__ w_b1, const float* __restrict__ b_b1,
                       const float* __restrict__ w_b2, const float* __restrict__ b_b2) {
    int t = blockIdx.x * blockDim.x + threadIdx.x;
    if (t >= 4096) return;
    int u = index[t];
    float dx = delta[2 * u], dy = delta[2 * u + 1];
    float acc = b_b2[0];
#pragma unroll
    for (int j = 0; j < 16; ++j) {
        float h = dx * w_b1[2 * j] + dy * w_b1[2 * j + 1] + b_b1[j];
        acc += w_b2[j] * gelu_exact(h);
    }
    g_bias[t] = acc;
}

// ---------------------------------------------------------------------------
// Kernel 0b: pre-pack conv2 weights per-tap hi/lo (row-major co x ci)
// ---------------------------------------------------------------------------
__global__ void k_wpack(const float* __restrict__ w_c2) {
    int idx = blockIdx.x * blockDim.x + threadIdx.x;
    if (idx >= 9 * 128 * 128) return;
    int tap = idx / 16384;
    int r   = idx & 16383;
    int co  = r >> 7, ci = r & 127;
    float v = w_c2[(size_t)(co * 128 + ci) * 9 + tap];
    unsigned short h, l; hl1(v, h, l);
    unsigned short* base = g_w2pk + tap * 32768;
    base[co * 128 + ci]         = h;
    base[16384 + co * 128 + ci] = l;
}

// ---------------------------------------------------------------------------
// Kernel 0c: pre-pack linear weights (w_qkv | w_head | w_c1) hi/lo
// ---------------------------------------------------------------------------
__global__ void k_wpackL(const float* __restrict__ w_qkv, const float* __restrict__ w_head,
                         const float* __restrict__ w_c1) {
    int idx = blockIdx.x * blockDim.x + threadIdx.x;
    if (idx >= 640 * 128) return;
    int row = idx >> 7, ci = idx & 127;
    float v = (row < 384) ? w_qkv[idx]
            : (row < 512) ? w_head[(row - 384) * 128 + ci]
                          : w_c1[(row - 512) * 128 + ci];
    unsigned short h, l; hl1(v, h, l);
    g_lwh[idx] = h; g_lwl[idx] = l;
}

// ---------------------------------------------------------------------------
// Kernel 1: window attention, PLAIN bf16 mma (errors damped ~150x by residual).
// smem (shorts), total 52736 = 105,472 B -> 2 CTAs/SM:
//   XB 0     (64x136 x bf16; after softmax reused as probs PB [2][64][68])
//   QB 8704  (q)
//   KB 17408 (k; after P4 reused as attention-out O)
//   VT 26112 (v^T [128][72])
//   WB 35328 (weights [128][136]; P3 overlay: SC fp32 [2][64][66])
// ---------------------------------------------------------------------------
__global__ void __launch_bounds__(256, 2)
k_attn(const float* __restrict__ x,
       const float* __restrict__ b_qkv, const float* __restrict__ b_head) {
    unsigned short* S  = (unsigned short*)smem;
    unsigned short* XB = S;
    unsigned short* QB = S + 8704;
    unsigned short* KB = S + 17408;
    unsigned short* VT = S + 26112;
    unsigned short* WB = S + 35328;
    float* SC = (float*)(S + 35328);
    unsigned short* PB = XB;      // probs after softmax, stride 68
    unsigned short* OB = KB;      // attention out after P4

    const int tid = threadIdx.x;
    const int warp = tid >> 5, lane = tid & 31;
    const int g = lane >> 2, tig = lane & 3;
    const int wid = blockIdx.x;
    const int b   = wid >> 10;
    const int ohi = (wid >> 5) & 31;
    const int owi = wid & 31;
    const float* xptr = x + (size_t)b * CC * HW + ohi * 8 * 256 + owi * 8;

    const int m0 = (warp & 3) * 16;
    const int n0 = (warp >> 2) * 64;

    // ---- P1: load x window -> XB (bf16); stage W chunk 0 ----
    for (int e = tid; e < 8192; e += 256) {
        int c = e >> 6, n = e & 63;
        XB[n * CI_S + c] = bf1(xptr[(size_t)c * HW + (n >> 3) * 256 + (n & 7)]);
    }
    for (int e = tid; e < 2048; e += 256) {
        int n = e >> 4, c8 = e & 15;
        *(uint4*)(WB + n * CI_S + c8 * 8) = *(const uint4*)(g_lwh + n * 128 + c8 * 8);
    }
    __syncthreads();

    // ---- P2: qkv projection, three 128-co chunks ----
    for (int cc = 0; cc < 3; ++cc) {
        if (cc) {
            __syncthreads();
            for (int e = tid; e < 2048; e += 256) {
                int n = e >> 4, c8 = e & 15;
                *(uint4*)(WB + n * CI_S + c8 * 8) =
                    *(const uint4*)(g_lwh + (cc * 128 + n) * 128 + c8 * 8);
            }
            __syncthreads();
        }
        float acc[8][4];
#pragma unroll
        for (int nf = 0; nf < 8; ++nf)
#pragma unroll
            for (int q = 0; q < 4; ++q) acc[nf][q] = 0.f;
#pragma unroll
        for (int ks = 0; ks < 8; ++ks) {
            int k0 = ks * 16 + 2 * tig;
            mma1_8(acc, XB + (m0 + g) * CI_S + k0, CI_S, WB + (n0 + g) * CI_S + k0, CI_S);
        }
#pragma unroll
        for (int nf = 0; nf < 8; ++nf) {
            int col = n0 + nf * 8 + 2 * tig;
            float bq0 = b_qkv[cc * 128 + col], bq1 = b_qkv[cc * 128 + col + 1];
            int r0 = m0 + g, r1 = m0 + g + 8;
            float v00 = acc[nf][0] + bq0, v01 = acc[nf][1] + bq1;
            float v10 = acc[nf][2] + bq0, v11 = acc[nf][3] + bq1;
            if (cc == 0) {
                *(uint32_t*)(QB + r0 * CI_S + col) = pk1(v00, v01);
                *(uint32_t*)(QB + r1 * CI_S + col) = pk1(v10, v11);
            } else if (cc == 1) {
                *(uint32_t*)(KB + r0 * CI_S + col) = pk1(v00, v01);
                *(uint32_t*)(KB + r1 * CI_S + col) = pk1(v10, v11);
            } else {
                VT[col * 72 + r0]       = bf1(v00);
                VT[(col + 1) * 72 + r0] = bf1(v01);
                VT[col * 72 + r1]       = bf1(v10);
                VT[(col + 1) * 72 + r1] = bf1(v11);
            }
        }
    }
    __syncthreads();

    // ---- P3: scores = q k^T * 0.125 + bias -> SC (fp32, WB overlay) ----
    {
        const int hd = warp >> 2, mq = (warp & 3) * 16;
        float acc[8][4];
#pragma unroll
        for (int nf = 0; nf < 8; ++nf)
#pragma unroll
            for (int q = 0; q < 4; ++q) acc[nf][q] = 0.f;
#pragma unroll
        for (int ks = 0; ks < 4; ++ks) {
            int k0 = hd * 64 + ks * 16 + 2 * tig;
            mma1_8(acc, QB + (mq + g) * CI_S + k0, CI_S, KB + g * CI_S + k0, CI_S);
        }
        float* sc = SC + hd * 4224;
#pragma unroll
        for (int nf = 0; nf < 8; ++nf) {
            int col = nf * 8 + 2 * tig;
            int r0 = mq + g, r1 = mq + g + 8;
            sc[r0 * 66 + col]     = acc[nf][0] * 0.125f + g_bias[r0 * 64 + col];
            sc[r0 * 66 + col + 1] = acc[nf][1] * 0.125f + g_bias[r0 * 64 + col + 1];
            sc[r1 * 66 + col]     = acc[nf][2] * 0.125f + g_bias[r1 * 64 + col];
            sc[r1 * 66 + col + 1] = acc[nf][3] * 0.125f + g_bias[r1 * 64 + col + 1];
        }
    }
    __syncthreads();

    // ---- softmax (fp32) -> probs bf16 into PB (XB region, stride 68) ----
    {
        int rid = tid >> 1, hd = rid >> 6, row = rid & 63, sub = tid & 1;
        float* r = SC + hd * 4224 + row * 66 + sub * 32;
        float v[32];
        float mx = -1e30f;
#pragma unroll
        for (int m = 0; m < 32; ++m) { v[m] = r[m]; mx = fmaxf(mx, v[m]); }
        mx = fmaxf(mx, __shfl_xor_sync(0xffffffffu, mx, 1));
        float s = 0.f;
#pragma unroll
        for (int m = 0; m < 32; ++m) { v[m] = __expf(v[m] - mx); s += v[m]; }
        s += __shfl_xor_sync(0xffffffffu, s, 1);
        float inv = 1.f / s;
        __syncthreads();   // XB (x) fully consumed by P2 before overwrite
        int base = hd * 4352 + row * 68 + sub * 32;
#pragma unroll
        for (int m = 0; m < 32; m += 2)
            *(uint32_t*)(PB + base + m) = pk1(v[m] * inv, v[m + 1] * inv);
    }
    __syncthreads();

    // ---- P4: o = p @ v -> OB (KB region) ----
    {
        const int hd = warp >> 2, mq = (warp & 3) * 16;
        float acc[8][4];
#pragma unroll
        for (int nf = 0; nf < 8; ++nf)
#pragma unroll
            for (int q = 0; q < 4; ++q) acc[nf][q] = 0.f;
#pragma unroll
        for (int ks = 0; ks < 4; ++ks) {
            int k0 = ks * 16 + 2 * tig;
            mma1_8(acc, PB + hd * 4352 + (mq + g) * 68 + k0, 68,
                        VT + (hd * 64 + g) * 72 + k0, 72);
        }
        __syncthreads();   // KB (k) consumed in P3; ensure all P3/P4 reads done
#pragma unroll
        for (int nf = 0; nf < 8; ++nf) {
            int col = hd * 64 + nf * 8 + 2 * tig;
            int r0 = mq + g, r1 = mq + g + 8;
            *(uint32_t*)(OB + r0 * CI_S + col) = pk1(acc[nf][0], acc[nf][1]);
            *(uint32_t*)(OB + r1 * CI_S + col) = pk1(acc[nf][2], acc[nf][3]);
        }
    }
    __syncthreads();

    // ---- P5: head proj + residual(x from gmem, fp32-exact) ----
    for (int e = tid; e < 2048; e += 256) {
        int n = e >> 4, c8 = e & 15;
        *(uint4*)(WB + n * CI_S + c8 * 8) = *(const uint4*)(g_lwh + (384 + n) * 128 + c8 * 8);
    }
    __syncthreads();
    {
        float acc[8][4];
#pragma unroll
        for (int nf = 0; nf < 8; ++nf)
#pragma unroll
            for (int q = 0; q < 4; ++q) acc[nf][q] = 0.f;
#pragma unroll
        for (int ks = 0; ks < 8; ++ks) {
            int k0 = ks * 16 + 2 * tig;
            mma1_8(acc, OB + (m0 + g) * CI_S + k0, CI_S, WB + (n0 + g) * CI_S + k0, CI_S);
        }
#pragma unroll
        for (int nf = 0; nf < 8; ++nf) {
            int co = n0 + nf * 8 + 2 * tig;
            float bh0 = b_head[co], bh1 = b_head[co + 1];
#pragma unroll
            for (int half = 0; half < 2; ++half) {
                int tok = m0 + g + half * 8;
                int prow = ohi * 8 + (tok >> 3), pcol = owi * 8 + (tok & 7);
                float x0 = xptr[(size_t)co * HW + (tok >> 3) * 256 + (tok & 7)];
                float x1 = xptr[(size_t)(co + 1) * HW + (tok >> 3) * 256 + (tok & 7)];
                float o0 = acc[nf][half * 2]     + bh0 + x0;
                float o1 = acc[nf][half * 2 + 1] + bh1 + x1;
                size_t pix = (size_t)(b * HW + prow * 256 + pcol);
                g_x2[((size_t)(b * 128 + co)) * HW + prow * 256 + pcol]     = o0;
                g_x2[((size_t)(b * 128 + co + 1)) * HW + prow * 256 + pcol] = o1;
                uint32_t lo, hi = pkhl(o0, o1, lo);
                *(uint32_t*)(g_x2h + pix * 128 + co) = hi;
                *(uint32_t*)(g_x2l + pix * 128 + co) = lo;
            }
        }
    }
}

// ---------------------------------------------------------------------------
// Kernel 2: 1x1 conv + exact GELU, 3-term hi/lo (conv errors are undamped).
// Block = 64 px x 128 co, 4096 blocks. smem 52224 shorts = 104,448 B -> 2/SM.
// ---------------------------------------------------------------------------
__global__ void __launch_bounds__(256, 2)
k_conv1(const float* __restrict__ b_c1) {
    unsigned short* S  = (unsigned short*)smem;
    unsigned short* WH = S;
    unsigned short* WL = S + 17408;
    unsigned short* BHt = S + 34816;   // 64 x 136
    unsigned short* BLt = S + 43520;
    const int tid = threadIdx.x, warp = tid >> 5, lane = tid & 31;
    const int g = lane >> 2, tig = lane & 3;
    const size_t px0 = (size_t)blockIdx.x * 64;

    for (int e = tid; e < 2048; e += 256) {
        int n = e >> 4, c8 = e & 15;
        int dst = n * CI_S + c8 * 8;
        int src = (512 + n) * 128 + c8 * 8;
        *(uint4*)(WH + dst) = *(const uint4*)(g_lwh + src);
        *(uint4*)(WL + dst) = *(const uint4*)(g_lwl + src);
    }
    for (int e = tid; e < 1024; e += 256) {
        int p = e >> 4, c8 = e & 15;
        int dst = p * CI_S + c8 * 8;
        size_t src = (px0 + p) * 128 + c8 * 8;
        *(uint4*)(BHt + dst) = *(const uint4*)(g_x2h + src);
        *(uint4*)(BLt + dst) = *(const uint4*)(g_x2l + src);
    }
    __syncthreads();

    const int m0 = (warp & 3) * 16;     // px
    const int n0 = (warp >> 2) * 64;    // co
    float acc[8][4];
#pragma unroll
    for (int nf = 0; nf < 8; ++nf)
#pragma unroll
        for (int q = 0; q < 4; ++q) acc[nf][q] = 0.f;

#pragma unroll
    for (int ks = 0; ks < 8; ++ks) {
        int k0 = ks * 16 + 2 * tig;
        mma3_8(acc, BHt + (m0 + g) * CI_S + k0, BLt + (m0 + g) * CI_S + k0, CI_S,
                    WH + (n0 + g) * CI_S + k0, WL + (n0 + g) * CI_S + k0, CI_S);
    }

#pragma unroll
    for (int nf = 0; nf < 8; ++nf) {
        int co = n0 + nf * 8 + 2 * tig;
        float bc0 = b_c1[co], bc1 = b_c1[co + 1];
#pragma unroll
        for (int half = 0; half < 2; ++half) {
            size_t px = px0 + m0 + g + half * 8;
            float v0 = gelu_exact(acc[nf][half * 2] + bc0);
            float v1 = gelu_exact(acc[nf][half * 2 + 1] + bc1);
            uint32_t lo, hi = pkhl(v0, v1, lo);
            *(uint32_t*)(g_yh + px * 128 + co) = hi;
            *(uint32_t*)(g_yl + px * 128 + co) = lo;
        }
    }
}

// ---------------------------------------------------------------------------
// Kernel 3: 3x3 conv, 3-term hi/lo, cp.async 3-buffer weight pipeline.
// 27 stages (tap x split); each stages one 128x136 weight component while
// MMAs for the current stage run. One barrier per stage.
// smem (shorts): wbuf[3] @0/17408/34816, yH @52224 (204x136), yL @79968.
// Total 107,712 shorts = 215,424 B (1 CTA/SM).
// ---------------------------------------------------------------------------
__global__ void __launch_bounds__(256, 1)
k_conv2(const float* __restrict__ b_c2, float* __restrict__ out) {
    unsigned short* S  = (unsigned short*)smem;
    unsigned short* yH = S + 52224;
    unsigned short* yL = S + 79968;
    const uint32_t sbase = smem_u32(S);

    const int tid = threadIdx.x, warp = tid >> 5, lane = tid & 31;
    const int gid = lane >> 2, tig = lane & 3;
    const int c0 = (blockIdx.x & 7) * 32;
    const int r0 = ((blockIdx.x >> 3) & 63) * 4;
    const int b  = blockIdx.x >> 9;
    const int wq = warp & 3;
    const int rp = warp >> 2;

    // ---- y halo via cp.async (group 0, together with w-stage 0) ----
    for (int e = tid; e < 3264; e += 256) {
        int px = e >> 4, c16 = e & 15;
        int hr = px / 34, hc = px - hr * 34;
        int r = r0 + hr - 1; r = r < 0 ? 0 : (r > 255 ? 255 : r);
        int c = c0 + hc - 1; c = c < 0 ? 0 : (c > 255 ? 255 : c);
        size_t src = ((size_t)(b * 65536 + r * 256 + c)) * 128 + c16 * 8;
        uint32_t d = sbase + (uint32_t)(52224 + px * CI_S + c16 * 8) * 2;
        CP16(d, (const char*)(g_yh + src));
        CP16(d + 27744 * 2, (const char*)(g_yl + src));
    }
    // w-stage helper (lambda-style macro via loop)
#define STAGE_W(t) do { \
        int _tap = (t) / 3, _s = (t) % 3; \
        const unsigned short* _src = g_w2pk + _tap * 32768 + ((_s == 1) ? 16384 : 0); \
        uint32_t _dbase = sbase + (uint32_t)(((t) % 3) * 17408) * 2; \
        for (int _e = tid; _e < 2048; _e += 256) { \
            int _n = _e >> 4, _c8 = _e & 15; \
            CP16(_dbase + (uint32_t)(_n * CI_S + _c8 * 8) * 2, \
                 (const char*)(_src + _n * 128 + _c8 * 8)); \
        } \
    } while (0)

    STAGE_W(0);
    CPCOMMIT();
    STAGE_W(1);
    CPCOMMIT();

    float acc[2][8][4];
#pragma unroll
    for (int mi = 0; mi < 2; ++mi)
#pragma unroll
        for (int nf = 0; nf < 8; ++nf)
#pragma unroll
            for (int q = 0; q < 4; ++q) acc[mi][nf][q] = 0.f;

    for (int t = 0; t < 27; ++t) {
        CPWAIT1();
        __syncthreads();
        if (t + 2 < 27) STAGE_W(t + 2);
        CPCOMMIT();

        const int tap = t / 3, s = t % 3;
        const int ky = tap / 3, kx = tap - ky * 3;
        const unsigned short* Aw = S + (t % 3) * 17408;
        const unsigned short* By = (s == 2) ? yL : yH;

        int hb[8];
#pragma unroll
        for (int nf = 0; nf < 8; ++nf) {
            int rip = nf >> 2, colb = (nf & 3) * 8;
            hb[nf] = ((rp * 2 + rip + ky) * 34 + colb + gid + kx) * CI_S;
        }

#pragma unroll
        for (int kk = 0; kk < 8; ++kk) {
            const int k0 = kk * 16 + 2 * tig;
            uint32_t a[2][4], bb[8][2];
#pragma unroll
            for (int mi = 0; mi < 2; ++mi) {
                const unsigned short* ap = Aw + (wq * 32 + mi * 16 + gid) * CI_S + k0;
                a[mi][0] = *(const uint32_t*)(ap);
                a[mi][1] = *(const uint32_t*)(ap + 8 * CI_S);
                a[mi][2] = *(const uint32_t*)(ap + 8);
                a[mi][3] = *(const uint32_t*)(ap + 8 * CI_S + 8);
            }
#pragma unroll
            for (int nf = 0; nf < 8; ++nf) {
                const unsigned short* bp = By + hb[nf] + k0;
                bb[nf][0] = *(const uint32_t*)(bp);
                bb[nf][1] = *(const uint32_t*)(bp + 8);
            }
#pragma unroll
            for (int mi = 0; mi < 2; ++mi)
#pragma unroll
                for (int nf = 0; nf < 8; ++nf)
                    mma_bf16(acc[mi][nf], a[mi], bb[nf]);
        }
    }

#pragma unroll
    for (int mi = 0; mi < 2; ++mi) {
        const int co_lo = wq * 32 + mi * 16 + gid;
        const int co_hi = co_lo + 8;
        const float bl = b_c2[co_lo];
        const float bh2 = b_c2[co_hi];
#pragma unroll
        for (int nf = 0; nf < 8; ++nf) {
            int rip = nf >> 2;
            int col = c0 + (nf & 3) * 8 + 2 * tig;
            int row = r0 + rp * 2 + rip;
            {
                size_t adr = ((size_t)(b * 128 + co_lo)) * 65536 + (size_t)row * 256 + col;
                float2 res = *(const float2*)(g_x2 + adr);
                float v0 = acc[mi][nf][0] + bl;
                float v1 = acc[mi][nf][1] + bl;
                v0 = v0 > 0.f ? v0 : 0.1f * v0;
                v1 = v1 > 0.f ? v1 : 0.1f * v1;
                float2 o; o.x = res.x + v0; o.y = res.y + v1;
                *(float2*)(out + adr) = o;
            }
            {
                size_t adr = ((size_t)(b * 128 + co_hi)) * 65536 + (size_t)row * 256 + col;
                float2 res = *(const float2*)(g_x2 + adr);
                float v2 = acc[mi][nf][2] + bh2;
                float v3 = acc[mi][nf][3] + bh2;
                v2 = v2 > 0.f ? v2 : 0.1f * v2;
                v3 = v3 > 0.f ? v3 : 0.1f * v3;
                float2 o; o.x = res.x + v2; o.y = res.y + v3;
                *(float2*)(out + adr) = o;
            }
        }
    }
}

// ---------------------------------------------------------------------------
extern "C" void kernel_launch(void* const* d_in, const int* in_sizes, int n_in,
                              void* d_out, int out_size) {
    const float* x      = (const float*)d_in[0];
    const float* delta  = (const float*)d_in[1];
    const int*   index  = (const int*)d_in[2];
    const float* w_qkv  = (const float*)d_in[3];
    const float* b_qkv  = (const float*)d_in[4];
    const float* w_head = (const float*)d_in[5];
    const float* b_head = (const float*)d_in[6];
    const float* w_b1   = (const float*)d_in[7];
    const float* b_b1   = (const float*)d_in[8];
    const float* w_b2   = (const float*)d_in[9];
    const float* b_b2   = (const float*)d_in[10];
    const float* w_c1   = (const float*)d_in[11];
    const float* b_c1   = (const float*)d_in[12];
    const float* w_c2   = (const float*)d_in[13];
    const float* b_c2   = (const float*)d_in[14];
    float* out = (float*)d_out;

    const int attn_smem = 52736 * 2;    // 105,472 B (2 CTAs/SM)
    const int c1_smem   = 52224 * 2;    // 104,448 B (2 CTAs/SM)
    const int c2_smem   = 107712 * 2;   // 215,424 B
    cudaFuncSetAttribute(k_attn,  cudaFuncAttributeMaxDynamicSharedMemorySize, attn_smem);
    cudaFuncSetAttribute(k_conv1, cudaFuncAttributeMaxDynamicSharedMemorySize, c1_smem);
    cudaFuncSetAttribute(k_conv2, cudaFuncAttributeMaxDynamicSharedMemorySize, c2_smem);

    k_bias  <<<16, 256>>>(delta, index, w_b1, b_b1, w_b2, b_b2);
    k_wpack <<<576, 256>>>(w_c2);
    k_wpackL<<<320, 256>>>(w_qkv, w_head, w_c1);
    k_attn  <<<4096, 256, attn_smem>>>(x, b_qkv, b_head);
    k_conv1 <<<4096, 256, c1_smem>>>(b_c1);
    k_conv2 <<<2048, 256, c2_smem>>>(b_c2, out);
}

// round 14
// speedup vs baseline: 6.7308x; 2.1642x over previous
#include <cuda_runtime.h>
#include <cuda_bf16.h>
#include <cuda_fp16.h>
#include <stdint.h>
#include <math.h>

// Problem constants
#define CC   128
#define HW   65536
#define CI_S 136          // padded k-stride (shorts) -> conflict-free fragment LDS

// Scratch (device globals; no cudaMalloc allowed)
__device__ float g_bias[64 * 64];
__device__ float g_x2[4 * CC * HW];              // x + attention residual (NCHW fp32)
__device__ unsigned short g_x2f[4 * HW * CC];    // x2, NHWC f16
__device__ unsigned short g_yf[4 * HW * CC];     // gelu(conv1), NHWC f16
__device__ uint32_t g_awb[32768];                // attn W bf16 B-frags: ((nt*8+ks)*32+lane)*2+w ; nt 0-47 qkv, 48-63 head
__device__ uint32_t g_c1wb[8192];                // conv1 W f16 B-frags: ((nt*8+ks)*32+lane)*2+w
__device__ uint32_t g_c2wa[73728];               // conv2 W f16 A-frags: (((tap*8+mt)*8+ks)*32+lane)*4+w

__device__ __forceinline__ float gelu_exact(float v) {
    return 0.5f * v * (1.0f + erff(v * 0.70710678118654752440f));
}

extern __shared__ float smem[];

__device__ __forceinline__ void mma_bf16(float* d, const uint32_t* a, const uint32_t* b) {
    asm volatile(
        "mma.sync.aligned.m16n8k16.row.col.f32.bf16.bf16.f32 "
        "{%0,%1,%2,%3}, {%4,%5,%6,%7}, {%8,%9}, {%0,%1,%2,%3};\n"
        : "+f"(d[0]), "+f"(d[1]), "+f"(d[2]), "+f"(d[3])
        : "r"(a[0]), "r"(a[1]), "r"(a[2]), "r"(a[3]), "r"(b[0]), "r"(b[1]));
}
__device__ __forceinline__ void mma_f16(float* d, const uint32_t* a, const uint32_t* b) {
    asm volatile(
        "mma.sync.aligned.m16n8k16.row.col.f32.f16.f16.f32 "
        "{%0,%1,%2,%3}, {%4,%5,%6,%7}, {%8,%9}, {%0,%1,%2,%3};\n"
        : "+f"(d[0]), "+f"(d[1]), "+f"(d[2]), "+f"(d[3])
        : "r"(a[0]), "r"(a[1]), "r"(a[2]), "r"(a[3]), "r"(b[0]), "r"(b[1]));
}

// smem-B variant (bf16): one m16 k16 step against 8 n-frags
__device__ __forceinline__ void mma1_8(float (*acc)[4],
    const unsigned short* a_p, const int astr,
    const unsigned short* b_p, const int bstr)
{
    uint32_t a[4], bb[2];
    a[0] = *(const uint32_t*)(a_p);
    a[1] = *(const uint32_t*)(a_p + 8 * astr);
    a[2] = *(const uint32_t*)(a_p + 8);
    a[3] = *(const uint32_t*)(a_p + 8 * astr + 8);
#pragma unroll
    for (int nf = 0; nf < 8; ++nf) {
        const unsigned short* bp = b_p + nf * 8 * bstr;
        bb[0] = *(const uint32_t*)(bp);
        bb[1] = *(const uint32_t*)(bp + 8);
        mma_bf16(acc[nf], a, bb);
    }
}

__device__ __forceinline__ unsigned short bf1(float v) {
    __nv_bfloat16 hb = __float2bfloat16(v);
    return *(unsigned short*)&hb;
}
__device__ __forceinline__ uint32_t pk1(float v0, float v1) {
    __nv_bfloat16 h0 = __float2bfloat16(v0), h1 = __float2bfloat16(v1);
    return ((uint32_t)(*(unsigned short*)&h1) << 16) | (*(unsigned short*)&h0);
}
__device__ __forceinline__ uint32_t pk1h(float v0, float v1) {
    __half h0 = __float2half(v0), h1 = __float2half(v1);
    return ((uint32_t)(*(unsigned short*)&h1) << 16) | (*(unsigned short*)&h0);
}

// ---------------------------------------------------------------------------
// Kernel 0: relative-position bias MLP
// ---------------------------------------------------------------------------
__global__ void k_bias(const float* __restrict__ delta, const int* __restrict__ index,
                       const float* __restrict__ w_b1, const float* __restrict__ b_b1,
                       const float* __restrict__ w_b2, const float* __restrict__ b_b2) {
    int t = blockIdx.x * blockDim.x + threadIdx.x;
    if (t >= 4096) return;
    int u = index[t];
    float dx = delta[2 * u], dy = delta[2 * u + 1];
    float acc = b_b2[0];
#pragma unroll
    for (int j = 0; j < 16; ++j) {
        float h = dx * w_b1[2 * j] + dy * w_b1[2 * j + 1] + b_b1[j];
        acc += w_b2[j] * gelu_exact(h);
    }
    g_bias[t] = acc;
}

// ---------------------------------------------------------------------------
// Kernel 0a: attention weights (qkv|head) -> bf16 B-fragment order
// ---------------------------------------------------------------------------
__global__ void k_wpackA(const float* __restrict__ w_qkv, const float* __restrict__ w_head) {
    int idx = blockIdx.x * blockDim.x + threadIdx.x;
    if (idx >= 32768) return;
    int w = idx & 1, lane = (idx >> 1) & 31, ks = (idx >> 6) & 7, nt = idx >> 9;
    int n = nt * 8 + (lane >> 2);
    int k = ks * 16 + 2 * (lane & 3) + w * 8;
    float v0, v1;
    if (n < 384) { v0 = w_qkv[n * 128 + k]; v1 = w_qkv[n * 128 + k + 1]; }
    else { v0 = w_head[(n - 384) * 128 + k]; v1 = w_head[(n - 384) * 128 + k + 1]; }
    g_awb[idx] = pk1(v0, v1);
}

// ---------------------------------------------------------------------------
// Kernel 0b: conv1 weights -> f16 B-fragment order
// ---------------------------------------------------------------------------
__global__ void k_wpackC1(const float* __restrict__ w_c1) {
    int idx = blockIdx.x * blockDim.x + threadIdx.x;
    if (idx >= 8192) return;
    int w = idx & 1, lane = (idx >> 1) & 31, ks = (idx >> 6) & 7, nt = idx >> 9;
    int co = nt * 8 + (lane >> 2);
    int ci = ks * 16 + 2 * (lane & 3) + w * 8;
    g_c1wb[idx] = pk1h(w_c1[co * 128 + ci], w_c1[co * 128 + ci + 1]);
}

// ---------------------------------------------------------------------------
// Kernel 0c: conv2 weights -> f16 A-fragment order, per tap
// ---------------------------------------------------------------------------
__global__ void k_wpackC2(const float* __restrict__ w_c2) {
    int idx = blockIdx.x * blockDim.x + threadIdx.x;
    if (idx >= 73728) return;
    int w = idx & 3, lane = (idx >> 2) & 31, ks = (idx >> 7) & 7, mt = (idx >> 10) & 7, tap = idx >> 13;
    int m  = mt * 16 + (lane >> 2) + (w & 1) * 8;              // co
    int kb = ks * 16 + 2 * (lane & 3) + ((w >> 1) & 1) * 8;    // ci
    g_c2wa[idx] = pk1h(w_c2[(size_t)(m * 128 + kb) * 9 + tap],
                       w_c2[(size_t)(m * 128 + kb + 1) * 9 + tap]);
}

// ---------------------------------------------------------------------------
// Kernel 1: window attention, plain bf16 mma, weights from frag-packed gmem,
// register softmax. smem 35328 shorts = 70,656 B -> 3 CTAs/SM.
//   XB 0 (64x136; after softmax reused as probs PB [2][64][68])
//   QB 8704  KB 17408 (after P4 reused as O)  VT 26112 (v^T [128][72])
// ---------------------------------------------------------------------------
__global__ void __launch_bounds__(256, 3)
k_attn(const float* __restrict__ x,
       const float* __restrict__ b_qkv, const float* __restrict__ b_head) {
    unsigned short* S  = (unsigned short*)smem;
    unsigned short* XB = S;
    unsigned short* QB = S + 8704;
    unsigned short* KB = S + 17408;
    unsigned short* VT = S + 26112;
    unsigned short* PB = XB;
    unsigned short* OB = KB;

    const int tid = threadIdx.x;
    const int warp = tid >> 5, lane = tid & 31;
    const int g = lane >> 2, tig = lane & 3;
    const int wid = blockIdx.x;
    const int b   = wid >> 10;
    const int ohi = (wid >> 5) & 31;
    const int owi = wid & 31;
    const float* xptr = x + (size_t)b * CC * HW + ohi * 8 * 256 + owi * 8;

    const int m0 = (warp & 3) * 16;
    const int n0 = (warp >> 2) * 64;

    // ---- P1: load x window -> XB (bf16) ----
    for (int e = tid; e < 8192; e += 256) {
        int c = e >> 6, n = e & 63;
        XB[n * CI_S + c] = bf1(xptr[(size_t)c * HW + (n >> 3) * 256 + (n & 7)]);
    }
    __syncthreads();

    // ---- P2: qkv projection (weights from gmem frags, no barriers between chunks) ----
#pragma unroll 1
    for (int cc = 0; cc < 3; ++cc) {
        float acc[8][4];
#pragma unroll
        for (int nf = 0; nf < 8; ++nf)
#pragma unroll
            for (int q = 0; q < 4; ++q) acc[nf][q] = 0.f;
#pragma unroll
        for (int ks = 0; ks < 8; ++ks) {
            int k0 = ks * 16 + 2 * tig;
            uint32_t a[4];
            const unsigned short* ap = XB + (m0 + g) * CI_S + k0;
            a[0] = *(const uint32_t*)(ap);
            a[1] = *(const uint32_t*)(ap + 8 * CI_S);
            a[2] = *(const uint32_t*)(ap + 8);
            a[3] = *(const uint32_t*)(ap + 8 * CI_S + 8);
            const uint32_t* wp = g_awb + (((cc * 16 + (n0 >> 3)) * 8 + ks) * 32 + lane) * 2;
#pragma unroll
            for (int nf = 0; nf < 8; ++nf) {
                uint2 bq = *(const uint2*)(wp + nf * 512);
                uint32_t bb[2] = {bq.x, bq.y};
                mma_bf16(acc[nf], a, bb);
            }
        }
#pragma unroll
        for (int nf = 0; nf < 8; ++nf) {
            int col = n0 + nf * 8 + 2 * tig;
            float bq0 = b_qkv[cc * 128 + col], bq1 = b_qkv[cc * 128 + col + 1];
            int r0 = m0 + g, r1 = m0 + g + 8;
            float v00 = acc[nf][0] + bq0, v01 = acc[nf][1] + bq1;
            float v10 = acc[nf][2] + bq0, v11 = acc[nf][3] + bq1;
            if (cc == 0) {
                *(uint32_t*)(QB + r0 * CI_S + col) = pk1(v00, v01);
                *(uint32_t*)(QB + r1 * CI_S + col) = pk1(v10, v11);
            } else if (cc == 1) {
                *(uint32_t*)(KB + r0 * CI_S + col) = pk1(v00, v01);
                *(uint32_t*)(KB + r1 * CI_S + col) = pk1(v10, v11);
            } else {
                VT[col * 72 + r0]       = bf1(v00);
                VT[(col + 1) * 72 + r0] = bf1(v01);
                VT[col * 72 + r1]       = bf1(v10);
                VT[(col + 1) * 72 + r1] = bf1(v11);
            }
        }
    }
    __syncthreads();

    // ---- P3: scores + register softmax -> PB (bf16 probs) ----
    {
        const int hd = warp >> 2, mq = (warp & 3) * 16;
        float acc[8][4];
#pragma unroll
        for (int nf = 0; nf < 8; ++nf)
#pragma unroll
            for (int q = 0; q < 4; ++q) acc[nf][q] = 0.f;
#pragma unroll
        for (int ks = 0; ks < 4; ++ks) {
            int k0 = hd * 64 + ks * 16 + 2 * tig;
            mma1_8(acc, QB + (mq + g) * CI_S + k0, CI_S, KB + g * CI_S + k0, CI_S);
        }
        // bias + scale
#pragma unroll
        for (int nf = 0; nf < 8; ++nf) {
            int col = nf * 8 + 2 * tig;
            float2 b0 = *(const float2*)(g_bias + (mq + g) * 64 + col);
            float2 b1 = *(const float2*)(g_bias + (mq + g + 8) * 64 + col);
            acc[nf][0] = acc[nf][0] * 0.125f + b0.x;
            acc[nf][1] = acc[nf][1] * 0.125f + b0.y;
            acc[nf][2] = acc[nf][2] * 0.125f + b1.x;
            acc[nf][3] = acc[nf][3] * 0.125f + b1.y;
        }
        // row max (rows spread over the 4 lanes of a quad)
        float mx0 = -1e30f, mx1 = -1e30f;
#pragma unroll
        for (int nf = 0; nf < 8; ++nf) {
            mx0 = fmaxf(mx0, fmaxf(acc[nf][0], acc[nf][1]));
            mx1 = fmaxf(mx1, fmaxf(acc[nf][2], acc[nf][3]));
        }
        mx0 = fmaxf(mx0, __shfl_xor_sync(0xffffffffu, mx0, 1));
        mx0 = fmaxf(mx0, __shfl_xor_sync(0xffffffffu, mx0, 2));
        mx1 = fmaxf(mx1, __shfl_xor_sync(0xffffffffu, mx1, 1));
        mx1 = fmaxf(mx1, __shfl_xor_sync(0xffffffffu, mx1, 2));
        float s0 = 0.f, s1 = 0.f;
#pragma unroll
        for (int nf = 0; nf < 8; ++nf) {
            acc[nf][0] = __expf(acc[nf][0] - mx0); s0 += acc[nf][0];
            acc[nf][1] = __expf(acc[nf][1] - mx0); s0 += acc[nf][1];
            acc[nf][2] = __expf(acc[nf][2] - mx1); s1 += acc[nf][2];
            acc[nf][3] = __expf(acc[nf][3] - mx1); s1 += acc[nf][3];
        }
        s0 += __shfl_xor_sync(0xffffffffu, s0, 1);
        s0 += __shfl_xor_sync(0xffffffffu, s0, 2);
        s1 += __shfl_xor_sync(0xffffffffu, s1, 1);
        s1 += __shfl_xor_sync(0xffffffffu, s1, 2);
        float i0 = 1.f / s0, i1 = 1.f / s1;
        int base = hd * 4352;
#pragma unroll
        for (int nf = 0; nf < 8; ++nf) {
            int col = nf * 8 + 2 * tig;
            *(uint32_t*)(PB + base + (mq + g) * 68 + col)     = pk1(acc[nf][0] * i0, acc[nf][1] * i0);
            *(uint32_t*)(PB + base + (mq + g + 8) * 68 + col) = pk1(acc[nf][2] * i1, acc[nf][3] * i1);
        }
    }
    __syncthreads();

    // ---- P4: o = p @ v -> OB ----
    {
        const int hd = warp >> 2, mq = (warp & 3) * 16;
        float acc[8][4];
#pragma unroll
        for (int nf = 0; nf < 8; ++nf)
#pragma unroll
            for (int q = 0; q < 4; ++q) acc[nf][q] = 0.f;
#pragma unroll
        for (int ks = 0; ks < 4; ++ks) {
            int k0 = ks * 16 + 2 * tig;
            mma1_8(acc, PB + hd * 4352 + (mq + g) * 68 + k0, 68,
                        VT + (hd * 64 + g) * 72 + k0, 72);
        }
#pragma unroll
        for (int nf = 0; nf < 8; ++nf) {
            int col = hd * 64 + nf * 8 + 2 * tig;
            int r0 = mq + g, r1 = mq + g + 8;
            *(uint32_t*)(OB + r0 * CI_S + col) = pk1(acc[nf][0], acc[nf][1]);
            *(uint32_t*)(OB + r1 * CI_S + col) = pk1(acc[nf][2], acc[nf][3]);
        }
    }
    __syncthreads();

    // ---- P5: head proj + residual (x fp32 from gmem) ----
    {
        float acc[8][4];
#pragma unroll
        for (int nf = 0; nf < 8; ++nf)
#pragma unroll
            for (int q = 0; q < 4; ++q) acc[nf][q] = 0.f;
#pragma unroll
        for (int ks = 0; ks < 8; ++ks) {
            int k0 = ks * 16 + 2 * tig;
            uint32_t a[4];
            const unsigned short* ap = OB + (m0 + g) * CI_S + k0;
            a[0] = *(const uint32_t*)(ap);
            a[1] = *(const uint32_t*)(ap + 8 * CI_S);
            a[2] = *(const uint32_t*)(ap + 8);
            a[3] = *(const uint32_t*)(ap + 8 * CI_S + 8);
            const uint32_t* wp = g_awb + (((48 + (n0 >> 3)) * 8 + ks) * 32 + lane) * 2;
#pragma unroll
            for (int nf = 0; nf < 8; ++nf) {
                uint2 bq = *(const uint2*)(wp + nf * 512);
                uint32_t bb[2] = {bq.x, bq.y};
                mma_bf16(acc[nf], a, bb);
            }
        }
#pragma unroll
        for (int nf = 0; nf < 8; ++nf) {
            int co = n0 + nf * 8 + 2 * tig;
            float bh0 = b_head[co], bh1 = b_head[co + 1];
#pragma unroll
            for (int half = 0; half < 2; ++half) {
                int tok = m0 + g + half * 8;
                int prow = ohi * 8 + (tok >> 3), pcol = owi * 8 + (tok & 7);
                float x0 = xptr[(size_t)co * HW + (tok >> 3) * 256 + (tok & 7)];
                float x1 = xptr[(size_t)(co + 1) * HW + (tok >> 3) * 256 + (tok & 7)];
                float o0 = acc[nf][half * 2]     + bh0 + x0;
                float o1 = acc[nf][half * 2 + 1] + bh1 + x1;
                size_t pix = (size_t)(b * HW + prow * 256 + pcol);
                g_x2[((size_t)(b * 128 + co)) * HW + prow * 256 + pcol]     = o0;
                g_x2[((size_t)(b * 128 + co + 1)) * HW + prow * 256 + pcol] = o1;
                *(uint32_t*)(g_x2f + pix * 128 + co) = pk1h(o0, o1);
            }
        }
    }
}

// ---------------------------------------------------------------------------
// Kernel 2: 1x1 conv + exact GELU, single f16 mma, weights from gmem frags.
// Block = 64 px x 128 co. smem 8704 shorts = 17.4 KB -> 3 CTAs/SM.
// ---------------------------------------------------------------------------
__global__ void __launch_bounds__(256, 3)
k_conv1(const float* __restrict__ b_c1) {
    unsigned short* BT = (unsigned short*)smem;   // 64 x 136 f16
    const int tid = threadIdx.x, warp = tid >> 5, lane = tid & 31;
    const int g = lane >> 2, tig = lane & 3;
    const size_t px0 = (size_t)blockIdx.x * 64;

    for (int e = tid; e < 1024; e += 256) {
        int p = e >> 4, c8 = e & 15;
        *(uint4*)(BT + p * CI_S + c8 * 8) = *(const uint4*)(g_x2f + (px0 + p) * 128 + c8 * 8);
    }
    __syncthreads();

    const int m0 = (warp & 3) * 16;     // px
    const int n0 = (warp >> 2) * 64;    // co
    float acc[8][4];
#pragma unroll
    for (int nf = 0; nf < 8; ++nf)
#pragma unroll
        for (int q = 0; q < 4; ++q) acc[nf][q] = 0.f;

#pragma unroll
    for (int ks = 0; ks < 8; ++ks) {
        int k0 = ks * 16 + 2 * tig;
        uint32_t a[4];
        const unsigned short* ap = BT + (m0 + g) * CI_S + k0;
        a[0] = *(const uint32_t*)(ap);
        a[1] = *(const uint32_t*)(ap + 8 * CI_S);
        a[2] = *(const uint32_t*)(ap + 8);
        a[3] = *(const uint32_t*)(ap + 8 * CI_S + 8);
        const uint32_t* wp = g_c1wb + ((((n0 >> 3)) * 8 + ks) * 32 + lane) * 2;
#pragma unroll
        for (int nf = 0; nf < 8; ++nf) {
            uint2 bq = *(const uint2*)(wp + nf * 512);
            uint32_t bb[2] = {bq.x, bq.y};
            mma_f16(acc[nf], a, bb);
        }
    }

#pragma unroll
    for (int nf = 0; nf < 8; ++nf) {
        int co = n0 + nf * 8 + 2 * tig;
        float bc0 = b_c1[co], bc1 = b_c1[co + 1];
#pragma unroll
        for (int half = 0; half < 2; ++half) {
            size_t px = px0 + m0 + g + half * 8;
            float v0 = gelu_exact(acc[nf][half * 2] + bc0);
            float v1 = gelu_exact(acc[nf][half * 2 + 1] + bc1);
            *(uint32_t*)(g_yf + px * 128 + co) = pk1h(v0, v1);
        }
    }
}

// ---------------------------------------------------------------------------
// Kernel 3: 3x3 conv, single f16 mma, weights from gmem A-frags (L2-resident).
// Block = 128 co x (4 rows x 32 cols). smem = y halo only: 27744 shorts
// = 55.5 KB -> 2 CTAs/SM. One barrier total.
// ---------------------------------------------------------------------------
__global__ void __launch_bounds__(256, 2)
k_conv2(const float* __restrict__ b_c2, float* __restrict__ out) {
    unsigned short* yS = (unsigned short*)smem;   // 204 x 136 f16

    const int tid = threadIdx.x, warp = tid >> 5, lane = tid & 31;
    const int gid = lane >> 2, tig = lane & 3;
    const int c0 = (blockIdx.x & 7) * 32;
    const int r0 = ((blockIdx.x >> 3) & 63) * 4;
    const int b  = blockIdx.x >> 9;
    const int wq = warp & 3;
    const int rp = warp >> 2;

    for (int e = tid; e < 204 * 16; e += 256) {
        int px = e >> 4, c16 = e & 15;
        int hr = px / 34, hc = px - hr * 34;
        int r = r0 + hr - 1; r = r < 0 ? 0 : (r > 255 ? 255 : r);
        int c = c0 + hc - 1; c = c < 0 ? 0 : (c > 255 ? 255 : c);
        *(uint4*)(yS + px * CI_S + c16 * 8) =
            *(const uint4*)(g_yf + ((size_t)(b * 65536 + r * 256 + c)) * 128 + c16 * 8);
    }
    __syncthreads();

    float acc[2][8][4];
#pragma unroll
    for (int mi = 0; mi < 2; ++mi)
#pragma unroll
        for (int nf = 0; nf < 8; ++nf)
#pragma unroll
            for (int q = 0; q < 4; ++q) acc[mi][nf][q] = 0.f;

#pragma unroll 1
    for (int tap = 0; tap < 9; ++tap) {
        const int ky = tap / 3, kx = tap - ky * 3;
        int hb[8];
#pragma unroll
        for (int nf = 0; nf < 8; ++nf) {
            int rip = nf >> 2, colb = (nf & 3) * 8;
            hb[nf] = ((rp * 2 + rip + ky) * 34 + colb + gid + kx) * CI_S;
        }
#pragma unroll
        for (int ks = 0; ks < 8; ++ks) {
            const int k0 = ks * 16 + 2 * tig;
            const uint32_t* wp = g_c2wa + ((((tap * 8 + wq * 2) * 8 + ks) * 32) + lane) * 4;
            uint4 qa0 = *(const uint4*)(wp);
            uint4 qa1 = *(const uint4*)(wp + 1024);
            uint32_t a[2][4] = {{qa0.x, qa0.y, qa0.z, qa0.w}, {qa1.x, qa1.y, qa1.z, qa1.w}};
            uint32_t bb[8][2];
#pragma unroll
            for (int nf = 0; nf < 8; ++nf) {
                const unsigned short* bp = yS + hb[nf] + k0;
                bb[nf][0] = *(const uint32_t*)(bp);
                bb[nf][1] = *(const uint32_t*)(bp + 8);
            }
#pragma unroll
            for (int mi = 0; mi < 2; ++mi)
#pragma unroll
                for (int nf = 0; nf < 8; ++nf)
                    mma_f16(acc[mi][nf], a[mi], bb[nf]);
        }
    }

#pragma unroll
    for (int mi = 0; mi < 2; ++mi) {
        const int co_lo = wq * 32 + mi * 16 + gid;
        const int co_hi = co_lo + 8;
        const float bl = b_c2[co_lo];
        const float bh2 = b_c2[co_hi];
#pragma unroll
        for (int nf = 0; nf < 8; ++nf) {
            int rip = nf >> 2;
            int col = c0 + (nf & 3) * 8 + 2 * tig;
            int row = r0 + rp * 2 + rip;
            {
                size_t adr = ((size_t)(b * 128 + co_lo)) * 65536 + (size_t)row * 256 + col;
                float2 res = *(const float2*)(g_x2 + adr);
                float v0 = acc[mi][nf][0] + bl;
                float v1 = acc[mi][nf][1] + bl;
                v0 = v0 > 0.f ? v0 : 0.1f * v0;
                v1 = v1 > 0.f ? v1 : 0.1f * v1;
                float2 o; o.x = res.x + v0; o.y = res.y + v1;
                *(float2*)(out + adr) = o;
            }
            {
                size_t adr = ((size_t)(b * 128 + co_hi)) * 65536 + (size_t)row * 256 + col;
                float2 res = *(const float2*)(g_x2 + adr);
                float v2 = acc[mi][nf][2] + bh2;
                float v3 = acc[mi][nf][3] + bh2;
                v2 = v2 > 0.f ? v2 : 0.1f * v2;
                v3 = v3 > 0.f ? v3 : 0.1f * v3;
                float2 o; o.x = res.x + v2; o.y = res.y + v3;
                *(float2*)(out + adr) = o;
            }
        }
    }
}

// ---------------------------------------------------------------------------
extern "C" void kernel_launch(void* const* d_in, const int* in_sizes, int n_in,
                              void* d_out, int out_size) {
    const float* x      = (const float*)d_in[0];
    const float* delta  = (const float*)d_in[1];
    const int*   index  = (const int*)d_in[2];
    const float* w_qkv  = (const float*)d_in[3];
    const float* b_qkv  = (const float*)d_in[4];
    const float* w_head = (const float*)d_in[5];
    const float* b_head = (const float*)d_in[6];
    const float* w_b1   = (const float*)d_in[7];
    const float* b_b1   = (const float*)d_in[8];
    const float* w_b2   = (const float*)d_in[9];
    const float* b_b2   = (const float*)d_in[10];
    const float* w_c1   = (const float*)d_in[11];
    const float* b_c1   = (const float*)d_in[12];
    const float* w_c2   = (const float*)d_in[13];
    const float* b_c2   = (const float*)d_in[14];
    float* out = (float*)d_out;

    const int attn_smem = 35328 * 2;    // 70,656 B (3 CTAs/SM)
    const int c1_smem   = 8704 * 2;     // 17,408 B
    const int c2_smem   = 27744 * 2;    // 55,488 B (2 CTAs/SM)
    cudaFuncSetAttribute(k_attn,  cudaFuncAttributeMaxDynamicSharedMemorySize, attn_smem);
    cudaFuncSetAttribute(k_conv1, cudaFuncAttributeMaxDynamicSharedMemorySize, c1_smem);
    cudaFuncSetAttribute(k_conv2, cudaFuncAttributeMaxDynamicSharedMemorySize, c2_smem);

    k_bias   <<<16, 256>>>(delta, index, w_b1, b_b1, w_b2, b_b2);
    k_wpackA <<<128, 256>>>(w_qkv, w_head);
    k_wpackC1<<<32, 256>>>(w_c1);
    k_wpackC2<<<288, 256>>>(w_c2);
    k_attn   <<<4096, 256, attn_smem>>>(x, b_qkv, b_head);
    k_conv1  <<<4096, 256, c1_smem>>>(b_c1);
    k_conv2  <<<2048, 256, c2_smem>>>(b_c2, out);
}

// round 16
// speedup vs baseline: 7.5117x; 1.1160x over previous
#include <cuda_runtime.h>
#include <cuda_bf16.h>
#include <cuda_fp16.h>
#include <stdint.h>
#include <math.h>

// Problem constants
#define CC   128
#define HW   65536
#define CI_S 136          // padded k-stride (shorts) -> conflict-free fragment LDS

// Scratch (device globals; no cudaMalloc allowed)
__device__ float g_bias[64 * 64];
__device__ float g_x2[4 * CC * HW];              // x + attention residual (NCHW fp32)
__device__ unsigned short g_yf[4 * HW * CC];     // gelu(conv1), NHWC f16
__device__ uint32_t g_awb[32768];                // attn W bf16 B-frags: ((nt*8+ks)*32+lane)*2+w ; nt 0-47 qkv, 48-63 head
__device__ uint32_t g_c1wb[8192];                // conv1 W f16 B-frags
__device__ uint32_t g_c2wa[73728];               // conv2 W f16 A-frags: (((tap*8+mt)*8+ks)*32+lane)*4+w

__device__ __forceinline__ float gelu_exact(float v) {
    return 0.5f * v * (1.0f + erff(v * 0.70710678118654752440f));
}

extern __shared__ float smem[];

__device__ __forceinline__ uint32_t smem_u32(const void* p) {
    uint32_t a;
    asm("{ .reg .u64 t; cvta.to.shared.u64 t, %1; cvt.u32.u64 %0, t; }" : "=r"(a) : "l"(p));
    return a;
}
#define CP16(d, s) asm volatile("cp.async.cg.shared.global [%0], [%1], 16;\n" :: "r"(d), "l"(s))
#define CPCOMMIT() asm volatile("cp.async.commit_group;\n" ::: "memory")
#define CPWAIT0()  asm volatile("cp.async.wait_group 0;\n" ::: "memory")

__device__ __forceinline__ void mma_bf16(float* d, const uint32_t* a, const uint32_t* b) {
    asm volatile(
        "mma.sync.aligned.m16n8k16.row.col.f32.bf16.bf16.f32 "
        "{%0,%1,%2,%3}, {%4,%5,%6,%7}, {%8,%9}, {%0,%1,%2,%3};\n"
        : "+f"(d[0]), "+f"(d[1]), "+f"(d[2]), "+f"(d[3])
        : "r"(a[0]), "r"(a[1]), "r"(a[2]), "r"(a[3]), "r"(b[0]), "r"(b[1]));
}
__device__ __forceinline__ void mma_f16(float* d, const uint32_t* a, const uint32_t* b) {
    asm volatile(
        "mma.sync.aligned.m16n8k16.row.col.f32.f16.f16.f32 "
        "{%0,%1,%2,%3}, {%4,%5,%6,%7}, {%8,%9}, {%0,%1,%2,%3};\n"
        : "+f"(d[0]), "+f"(d[1]), "+f"(d[2]), "+f"(d[3])
        : "r"(a[0]), "r"(a[1]), "r"(a[2]), "r"(a[3]), "r"(b[0]), "r"(b[1]));
}

// smem-B bf16: one m16 k16 step against 8 n-frags
__device__ __forceinline__ void mma1_8(float (*acc)[4],
    const unsigned short* a_p, const int astr,
    const unsigned short* b_p, const int bstr)
{
    uint32_t a[4], bb[2];
    a[0] = *(const uint32_t*)(a_p);
    a[1] = *(const uint32_t*)(a_p + 8 * astr);
    a[2] = *(const uint32_t*)(a_p + 8);
    a[3] = *(const uint32_t*)(a_p + 8 * astr + 8);
#pragma unroll
    for (int nf = 0; nf < 8; ++nf) {
        const unsigned short* bp = b_p + nf * 8 * bstr;
        bb[0] = *(const uint32_t*)(bp);
        bb[1] = *(const uint32_t*)(bp + 8);
        mma_bf16(acc[nf], a, bb);
    }
}

__device__ __forceinline__ unsigned short bf1(float v) {
    __nv_bfloat16 hb = __float2bfloat16(v);
    return *(unsigned short*)&hb;
}
__device__ __forceinline__ uint32_t pk1(float v0, float v1) {
    __nv_bfloat16 h0 = __float2bfloat16(v0), h1 = __float2bfloat16(v1);
    return ((uint32_t)(*(unsigned short*)&h1) << 16) | (*(unsigned short*)&h0);
}
__device__ __forceinline__ uint32_t pk1h(float v0, float v1) {
    __half h0 = __float2half(v0), h1 = __float2half(v1);
    return ((uint32_t)(*(unsigned short*)&h1) << 16) | (*(unsigned short*)&h0);
}

// ---------------------------------------------------------------------------
// Kernel 0: relative-position bias MLP
// ---------------------------------------------------------------------------
__global__ void k_bias(const float* __restrict__ delta, const int* __restrict__ index,
                       const float* __restrict__ w_b1, const float* __restrict__ b_b1,
                       const float* __restrict__ w_b2, const float* __restrict__ b_b2) {
    int t = blockIdx.x * blockDim.x + threadIdx.x;
    if (t >= 4096) return;
    int u = index[t];
    float dx = delta[2 * u], dy = delta[2 * u + 1];
    float acc = b_b2[0];
#pragma unroll
    for (int j = 0; j < 16; ++j) {
        float h = dx * w_b1[2 * j] + dy * w_b1[2 * j + 1] + b_b1[j];
        acc += w_b2[j] * gelu_exact(h);
    }
    g_bias[t] = acc;
}

// ---------------------------------------------------------------------------
// Kernel 0a: attention weights (qkv|head) -> bf16 B-fragment order
// ---------------------------------------------------------------------------
__global__ void k_wpackA(const float* __restrict__ w_qkv, const float* __restrict__ w_head) {
    int idx = blockIdx.x * blockDim.x + threadIdx.x;
    if (idx >= 32768) return;
    int w = idx & 1, lane = (idx >> 1) & 31, ks = (idx >> 6) & 7, nt = idx >> 9;
    int n = nt * 8 + (lane >> 2);
    int k = ks * 16 + 2 * (lane & 3) + w * 8;
    float v0, v1;
    if (n < 384) { v0 = w_qkv[n * 128 + k]; v1 = w_qkv[n * 128 + k + 1]; }
    else { v0 = w_head[(n - 384) * 128 + k]; v1 = w_head[(n - 384) * 128 + k + 1]; }
    g_awb[idx] = pk1(v0, v1);
}

// ---------------------------------------------------------------------------
// Kernel 0b: conv1 weights -> f16 B-fragment order
// ---------------------------------------------------------------------------
__global__ void k_wpackC1(const float* __restrict__ w_c1) {
    int idx = blockIdx.x * blockDim.x + threadIdx.x;
    if (idx >= 8192) return;
    int w = idx & 1, lane = (idx >> 1) & 31, ks = (idx >> 6) & 7, nt = idx >> 9;
    int co = nt * 8 + (lane >> 2);
    int ci = ks * 16 + 2 * (lane & 3) + w * 8;
    g_c1wb[idx] = pk1h(w_c1[co * 128 + ci], w_c1[co * 128 + ci + 1]);
}

// ---------------------------------------------------------------------------
// Kernel 0c: conv2 weights -> f16 A-fragment order, per tap
// ---------------------------------------------------------------------------
__global__ void k_wpackC2(const float* __restrict__ w_c2) {
    int idx = blockIdx.x * blockDim.x + threadIdx.x;
    if (idx >= 73728) return;
    int w = idx & 3, lane = (idx >> 2) & 31, ks = (idx >> 7) & 7, mt = (idx >> 10) & 7, tap = idx >> 13;
    int m  = mt * 16 + (lane >> 2) + (w & 1) * 8;              // co
    int kb = ks * 16 + 2 * (lane & 3) + ((w >> 1) & 1) * 8;    // ci
    g_c2wa[idx] = pk1h(w_c2[(size_t)(m * 128 + kb) * 9 + tap],
                       w_c2[(size_t)(m * 128 + kb + 1) * 9 + tap]);
}

// ---------------------------------------------------------------------------
// Kernel 1: window attention + FUSED conv1. Plain bf16 attn mma, register
// softmax, f16 conv1 (P6) from smem-held x2. smem 35328 shorts = 70,656 B
// -> 3 CTAs/SM.
//   XB 0 (x bf16 [64][136]; -> probs PB; -> x2 f16 X2F for P6)
//   QB 8704  KB 17408 (-> O after P4)  VT 26112 (v^T [128][72])
// ---------------------------------------------------------------------------
__global__ void __launch_bounds__(256, 3)
k_attn(const float* __restrict__ x,
       const float* __restrict__ b_qkv, const float* __restrict__ b_head,
       const float* __restrict__ b_c1) {
    unsigned short* S  = (unsigned short*)smem;
    unsigned short* XB = S;
    unsigned short* QB = S + 8704;
    unsigned short* KB = S + 17408;
    unsigned short* VT = S + 26112;
    unsigned short* PB = XB;      // probs after softmax, stride 68
    unsigned short* OB = KB;      // attention out after P4
    unsigned short* X2F = XB;     // x2 f16 for P6 (stride CI_S)

    const int tid = threadIdx.x;
    const int warp = tid >> 5, lane = tid & 31;
    const int g = lane >> 2, tig = lane & 3;
    const int wid = blockIdx.x;
    const int b   = wid >> 10;
    const int ohi = (wid >> 5) & 31;
    const int owi = wid & 31;
    const float* xptr = x + (size_t)b * CC * HW + ohi * 8 * 256 + owi * 8;

    const int m0 = (warp & 3) * 16;
    const int n0 = (warp >> 2) * 64;

    // ---- P1: load x window -> XB (bf16) ----
    for (int e = tid; e < 8192; e += 256) {
        int c = e >> 6, n = e & 63;
        XB[n * CI_S + c] = bf1(xptr[(size_t)c * HW + (n >> 3) * 256 + (n & 7)]);
    }
    __syncthreads();

    // ---- P2: qkv projection (weights from gmem frags) ----
#pragma unroll 1
    for (int cc = 0; cc < 3; ++cc) {
        float acc[8][4];
#pragma unroll
        for (int nf = 0; nf < 8; ++nf)
#pragma unroll
            for (int q = 0; q < 4; ++q) acc[nf][q] = 0.f;
#pragma unroll
        for (int ks = 0; ks < 8; ++ks) {
            int k0 = ks * 16 + 2 * tig;
            uint32_t a[4];
            const unsigned short* ap = XB + (m0 + g) * CI_S + k0;
            a[0] = *(const uint32_t*)(ap);
            a[1] = *(const uint32_t*)(ap + 8 * CI_S);
            a[2] = *(const uint32_t*)(ap + 8);
            a[3] = *(const uint32_t*)(ap + 8 * CI_S + 8);
            const uint32_t* wp = g_awb + (((cc * 16 + (n0 >> 3)) * 8 + ks) * 32 + lane) * 2;
#pragma unroll
            for (int nf = 0; nf < 8; ++nf) {
                uint2 bq = *(const uint2*)(wp + nf * 512);
                uint32_t bb[2] = {bq.x, bq.y};
                mma_bf16(acc[nf], a, bb);
            }
        }
#pragma unroll
        for (int nf = 0; nf < 8; ++nf) {
            int col = n0 + nf * 8 + 2 * tig;
            float bq0 = b_qkv[cc * 128 + col], bq1 = b_qkv[cc * 128 + col + 1];
            int r0 = m0 + g, r1 = m0 + g + 8;
            float v00 = acc[nf][0] + bq0, v01 = acc[nf][1] + bq1;
            float v10 = acc[nf][2] + bq0, v11 = acc[nf][3] + bq1;
            if (cc == 0) {
                *(uint32_t*)(QB + r0 * CI_S + col) = pk1(v00, v01);
                *(uint32_t*)(QB + r1 * CI_S + col) = pk1(v10, v11);
            } else if (cc == 1) {
                *(uint32_t*)(KB + r0 * CI_S + col) = pk1(v00, v01);
                *(uint32_t*)(KB + r1 * CI_S + col) = pk1(v10, v11);
            } else {
                VT[col * 72 + r0]       = bf1(v00);
                VT[(col + 1) * 72 + r0] = bf1(v01);
                VT[col * 72 + r1]       = bf1(v10);
                VT[(col + 1) * 72 + r1] = bf1(v11);
            }
        }
    }
    __syncthreads();

    // ---- P3: scores + register softmax -> PB (bf16 probs) ----
    {
        const int hd = warp >> 2, mq = (warp & 3) * 16;
        float acc[8][4];
#pragma unroll
        for (int nf = 0; nf < 8; ++nf)
#pragma unroll
            for (int q = 0; q < 4; ++q) acc[nf][q] = 0.f;
#pragma unroll
        for (int ks = 0; ks < 4; ++ks) {
            int k0 = hd * 64 + ks * 16 + 2 * tig;
            mma1_8(acc, QB + (mq + g) * CI_S + k0, CI_S, KB + g * CI_S + k0, CI_S);
        }
#pragma unroll
        for (int nf = 0; nf < 8; ++nf) {
            int col = nf * 8 + 2 * tig;
            float2 b0 = *(const float2*)(g_bias + (mq + g) * 64 + col);
            float2 b1 = *(const float2*)(g_bias + (mq + g + 8) * 64 + col);
            acc[nf][0] = acc[nf][0] * 0.125f + b0.x;
            acc[nf][1] = acc[nf][1] * 0.125f + b0.y;
            acc[nf][2] = acc[nf][2] * 0.125f + b1.x;
            acc[nf][3] = acc[nf][3] * 0.125f + b1.y;
        }
        float mx0 = -1e30f, mx1 = -1e30f;
#pragma unroll
        for (int nf = 0; nf < 8; ++nf) {
            mx0 = fmaxf(mx0, fmaxf(acc[nf][0], acc[nf][1]));
            mx1 = fmaxf(mx1, fmaxf(acc[nf][2], acc[nf][3]));
        }
        mx0 = fmaxf(mx0, __shfl_xor_sync(0xffffffffu, mx0, 1));
        mx0 = fmaxf(mx0, __shfl_xor_sync(0xffffffffu, mx0, 2));
        mx1 = fmaxf(mx1, __shfl_xor_sync(0xffffffffu, mx1, 1));
        mx1 = fmaxf(mx1, __shfl_xor_sync(0xffffffffu, mx1, 2));
        float s0 = 0.f, s1 = 0.f;
#pragma unroll
        for (int nf = 0; nf < 8; ++nf) {
            acc[nf][0] = __expf(acc[nf][0] - mx0); s0 += acc[nf][0];
            acc[nf][1] = __expf(acc[nf][1] - mx0); s0 += acc[nf][1];
            acc[nf][2] = __expf(acc[nf][2] - mx1); s1 += acc[nf][2];
            acc[nf][3] = __expf(acc[nf][3] - mx1); s1 += acc[nf][3];
        }
        s0 += __shfl_xor_sync(0xffffffffu, s0, 1);
        s0 += __shfl_xor_sync(0xffffffffu, s0, 2);
        s1 += __shfl_xor_sync(0xffffffffu, s1, 1);
        s1 += __shfl_xor_sync(0xffffffffu, s1, 2);
        float i0 = 1.f / s0, i1 = 1.f / s1;
        int base = hd * 4352;
#pragma unroll
        for (int nf = 0; nf < 8; ++nf) {
            int col = nf * 8 + 2 * tig;
            *(uint32_t*)(PB + base + (mq + g) * 68 + col)     = pk1(acc[nf][0] * i0, acc[nf][1] * i0);
            *(uint32_t*)(PB + base + (mq + g + 8) * 68 + col) = pk1(acc[nf][2] * i1, acc[nf][3] * i1);
        }
    }
    __syncthreads();

    // ---- P4: o = p @ v -> OB ----
    {
        const int hd = warp >> 2, mq = (warp & 3) * 16;
        float acc[8][4];
#pragma unroll
        for (int nf = 0; nf < 8; ++nf)
#pragma unroll
            for (int q = 0; q < 4; ++q) acc[nf][q] = 0.f;
#pragma unroll
        for (int ks = 0; ks < 4; ++ks) {
            int k0 = ks * 16 + 2 * tig;
            mma1_8(acc, PB + hd * 4352 + (mq + g) * 68 + k0, 68,
                        VT + (hd * 64 + g) * 72 + k0, 72);
        }
        __syncthreads();   // PB reads done before X2F overwrite in P5
#pragma unroll
        for (int nf = 0; nf < 8; ++nf) {
            int col = hd * 64 + nf * 8 + 2 * tig;
            int r0 = mq + g, r1 = mq + g + 8;
            *(uint32_t*)(OB + r0 * CI_S + col) = pk1(acc[nf][0], acc[nf][1]);
            *(uint32_t*)(OB + r1 * CI_S + col) = pk1(acc[nf][2], acc[nf][3]);
        }
    }
    __syncthreads();

    // ---- P5: head proj + residual (x fp32 from gmem) -> g_x2 + X2F smem ----
    {
        float acc[8][4];
#pragma unroll
        for (int nf = 0; nf < 8; ++nf)
#pragma unroll
            for (int q = 0; q < 4; ++q) acc[nf][q] = 0.f;
#pragma unroll
        for (int ks = 0; ks < 8; ++ks) {
            int k0 = ks * 16 + 2 * tig;
            uint32_t a[4];
            const unsigned short* ap = OB + (m0 + g) * CI_S + k0;
            a[0] = *(const uint32_t*)(ap);
            a[1] = *(const uint32_t*)(ap + 8 * CI_S);
            a[2] = *(const uint32_t*)(ap + 8);
            a[3] = *(const uint32_t*)(ap + 8 * CI_S + 8);
            const uint32_t* wp = g_awb + (((48 + (n0 >> 3)) * 8 + ks) * 32 + lane) * 2;
#pragma unroll
            for (int nf = 0; nf < 8; ++nf) {
                uint2 bq = *(const uint2*)(wp + nf * 512);
                uint32_t bb[2] = {bq.x, bq.y};
                mma_bf16(acc[nf], a, bb);
            }
        }
#pragma unroll
        for (int nf = 0; nf < 8; ++nf) {
            int co = n0 + nf * 8 + 2 * tig;
            float bh0 = b_head[co], bh1 = b_head[co + 1];
#pragma unroll
            for (int half = 0; half < 2; ++half) {
                int tok = m0 + g + half * 8;
                int prow = ohi * 8 + (tok >> 3), pcol = owi * 8 + (tok & 7);
                float x0 = xptr[(size_t)co * HW + (tok >> 3) * 256 + (tok & 7)];
                float x1 = xptr[(size_t)(co + 1) * HW + (tok >> 3) * 256 + (tok & 7)];
                float o0 = acc[nf][half * 2]     + bh0 + x0;
                float o1 = acc[nf][half * 2 + 1] + bh1 + x1;
                g_x2[((size_t)(b * 128 + co)) * HW + prow * 256 + pcol]     = o0;
                g_x2[((size_t)(b * 128 + co + 1)) * HW + prow * 256 + pcol] = o1;
                *(uint32_t*)(X2F + tok * CI_S + co) = pk1h(o0, o1);
            }
        }
    }
    __syncthreads();

    // ---- P6: FUSED conv1 = gelu(x2 @ w_c1^T + b_c1) -> g_yf (f16 NHWC) ----
    {
        float acc[8][4];
#pragma unroll
        for (int nf = 0; nf < 8; ++nf)
#pragma unroll
            for (int q = 0; q < 4; ++q) acc[nf][q] = 0.f;
#pragma unroll
        for (int ks = 0; ks < 8; ++ks) {
            int k0 = ks * 16 + 2 * tig;
            uint32_t a[4];
            const unsigned short* ap = X2F + (m0 + g) * CI_S + k0;
            a[0] = *(const uint32_t*)(ap);
            a[1] = *(const uint32_t*)(ap + 8 * CI_S);
            a[2] = *(const uint32_t*)(ap + 8);
            a[3] = *(const uint32_t*)(ap + 8 * CI_S + 8);
            const uint32_t* wp = g_c1wb + ((((n0 >> 3)) * 8 + ks) * 32 + lane) * 2;
#pragma unroll
            for (int nf = 0; nf < 8; ++nf) {
                uint2 bq = *(const uint2*)(wp + nf * 512);
                uint32_t bb[2] = {bq.x, bq.y};
                mma_f16(acc[nf], a, bb);
            }
        }
#pragma unroll
        for (int nf = 0; nf < 8; ++nf) {
            int co = n0 + nf * 8 + 2 * tig;
            float bc0 = b_c1[co], bc1 = b_c1[co + 1];
#pragma unroll
            for (int half = 0; half < 2; ++half) {
                int tok = m0 + g + half * 8;
                int prow = ohi * 8 + (tok >> 3), pcol = owi * 8 + (tok & 7);
                size_t pix = (size_t)(b * HW + prow * 256 + pcol);
                float v0 = gelu_exact(acc[nf][half * 2] + bc0);
                float v1 = gelu_exact(acc[nf][half * 2 + 1] + bc1);
                *(uint32_t*)(g_yf + pix * 128 + co) = pk1h(v0, v1);
            }
        }
    }
}

// ---------------------------------------------------------------------------
// Kernel 3: 3x3 conv, single f16 mma, weights from gmem A-frags (L2-resident).
// Halo staged via cp.async. Block = 128 co x (4 rows x 32 cols).
// smem 27744 shorts = 55.5 KB -> 2 CTAs/SM. One barrier total.
// ---------------------------------------------------------------------------
__global__ void __launch_bounds__(256, 2)
k_conv2(const float* __restrict__ b_c2, float* __restrict__ out) {
    unsigned short* yS = (unsigned short*)smem;   // 204 x 136 f16
    const uint32_t sbase = smem_u32(yS);

    const int tid = threadIdx.x, warp = tid >> 5, lane = tid & 31;
    const int gid = lane >> 2, tig = lane & 3;
    const int c0 = (blockIdx.x & 7) * 32;
    const int r0 = ((blockIdx.x >> 3) & 63) * 4;
    const int b  = blockIdx.x >> 9;
    const int wq = warp & 3;
    const int rp = warp >> 2;

    for (int e = tid; e < 204 * 16; e += 256) {
        int px = e >> 4, c16 = e & 15;
        int hr = px / 34, hc = px - hr * 34;
        int r = r0 + hr - 1; r = r < 0 ? 0 : (r > 255 ? 255 : r);
        int c = c0 + hc - 1; c = c < 0 ? 0 : (c > 255 ? 255 : c);
        CP16(sbase + (uint32_t)(px * CI_S + c16 * 8) * 2,
             (const char*)(g_yf + ((size_t)(b * 65536 + r * 256 + c)) * 128 + c16 * 8));
    }
    CPCOMMIT();
    CPWAIT0();
    __syncthreads();

    float acc[2][8][4];
#pragma unroll
    for (int mi = 0; mi < 2; ++mi)
#pragma unroll
        for (int nf = 0; nf < 8; ++nf)
#pragma unroll
            for (int q = 0; q < 4; ++q) acc[mi][nf][q] = 0.f;

#pragma unroll 1
    for (int tap = 0; tap < 9; ++tap) {
        const int ky = tap / 3, kx = tap - ky * 3;
        int hb[8];
#pragma unroll
        for (int nf = 0; nf < 8; ++nf) {
            int rip = nf >> 2, colb = (nf & 3) * 8;
            hb[nf] = ((rp * 2 + rip + ky) * 34 + colb + gid + kx) * CI_S;
        }
#pragma unroll
        for (int ks = 0; ks < 8; ++ks) {
            const int k0 = ks * 16 + 2 * tig;
            const uint32_t* wp = g_c2wa + ((((tap * 8 + wq * 2) * 8 + ks) * 32) + lane) * 4;
            uint4 qa0 = *(const uint4*)(wp);
            uint4 qa1 = *(const uint4*)(wp + 1024);
            uint32_t a[2][4] = {{qa0.x, qa0.y, qa0.z, qa0.w}, {qa1.x, qa1.y, qa1.z, qa1.w}};
            uint32_t bb[8][2];
#pragma unroll
            for (int nf = 0; nf < 8; ++nf) {
                const unsigned short* bp = yS + hb[nf] + k0;
                bb[nf][0] = *(const uint32_t*)(bp);
                bb[nf][1] = *(const uint32_t*)(bp + 8);
            }
#pragma unroll
            for (int mi = 0; mi < 2; ++mi)
#pragma unroll
                for (int nf = 0; nf < 8; ++nf)
                    mma_f16(acc[mi][nf], a[mi], bb[nf]);
        }
    }

#pragma unroll
    for (int mi = 0; mi < 2; ++mi) {
        const int co_lo = wq * 32 + mi * 16 + gid;
        const int co_hi = co_lo + 8;
        const float bl = b_c2[co_lo];
        const float bh2 = b_c2[co_hi];
#pragma unroll
        for (int nf = 0; nf < 8; ++nf) {
            int rip = nf >> 2;
            int col = c0 + (nf & 3) * 8 + 2 * tig;
            int row = r0 + rp * 2 + rip;
            {
                size_t adr = ((size_t)(b * 128 + co_lo)) * 65536 + (size_t)row * 256 + col;
                float2 res = *(const float2*)(g_x2 + adr);
                float v0 = acc[mi][nf][0] + bl;
                float v1 = acc[mi][nf][1] + bl;
                v0 = v0 > 0.f ? v0 : 0.1f * v0;
                v1 = v1 > 0.f ? v1 : 0.1f * v1;
                float2 o; o.x = res.x + v0; o.y = res.y + v1;
                *(float2*)(out + adr) = o;
            }
            {
                size_t adr = ((size_t)(b * 128 + co_hi)) * 65536 + (size_t)row * 256 + col;
                float2 res = *(const float2*)(g_x2 + adr);
                float v2 = acc[mi][nf][2] + bh2;
                float v3 = acc[mi][nf][3] + bh2;
                v2 = v2 > 0.f ? v2 : 0.1f * v2;
                v3 = v3 > 0.f ? v3 : 0.1f * v3;
                float2 o; o.x = res.x + v2; o.y = res.y + v3;
                *(float2*)(out + adr) = o;
            }
        }
    }
}

// ---------------------------------------------------------------------------
extern "C" void kernel_launch(void* const* d_in, const int* in_sizes, int n_in,
                              void* d_out, int out_size) {
    const float* x      = (const float*)d_in[0];
    const float* delta  = (const float*)d_in[1];
    const int*   index  = (const int*)d_in[2];
    const float* w_qkv  = (const float*)d_in[3];
    const float* b_qkv  = (const float*)d_in[4];
    const float* w_head = (const float*)d_in[5];
    const float* b_head = (const float*)d_in[6];
    const float* w_b1   = (const float*)d_in[7];
    const float* b_b1   = (const float*)d_in[8];
    const float* w_b2   = (const float*)d_in[9];
    const float* b_b2   = (const float*)d_in[10];
    const float* w_c1   = (const float*)d_in[11];
    const float* b_c1   = (const float*)d_in[12];
    const float* w_c2   = (const float*)d_in[13];
    const float* b_c2   = (const float*)d_in[14];
    float* out = (float*)d_out;

    const int attn_smem = 35328 * 2;    // 70,656 B (3 CTAs/SM)
    const int c2_smem   = 27744 * 2;    // 55,488 B (2 CTAs/SM)
    cudaFuncSetAttribute(k_attn,  cudaFuncAttributeMaxDynamicSharedMemorySize, attn_smem);
    cudaFuncSetAttribute(k_conv2, cudaFuncAttributeMaxDynamicSharedMemorySize, c2_smem);

    k_bias   <<<16, 256>>>(delta, index, w_b1, b_b1, w_b2, b_b2);
    k_wpackA <<<128, 256>>>(w_qkv, w_head);
    k_wpackC1<<<32, 256>>>(w_c1);
    k_wpackC2<<<288, 256>>>(w_c2);
    k_attn   <<<4096, 256, attn_smem>>>(x, b_qkv, b_head, b_c1);
    k_conv2  <<<2048, 256, c2_smem>>>(b_c2, out);
}